// round 1
// baseline (speedup 1.0000x reference)
#include <cuda_runtime.h>

#define SB   2
#define CIN  32
#define COUT 64
#define RANK 64
#define S    64
#define PVOL (S*S*S)   // 262144 = 2^18

// Scratch (alloc-free rule: device globals). 134 MB each.
__device__ float g_bufA[(size_t)SB * RANK * PVOL];
__device__ float g_bufB[(size_t)SB * RANK * PVOL];

// ---------------------------------------------------------------------------
// K1: channel contraction  y[b,r,p] = sum_c x[b,c,p] * Win[c,r]
// Block tile: 128 spatial positions x 64 ranks. Thread tile: 8r x 4p.
// ---------------------------------------------------------------------------
__global__ void __launch_bounds__(256) k1_chan(const float* __restrict__ x,
                                               const float* __restrict__ Win) {
    __shared__ float sW[CIN * RANK];   // 8 KB
    __shared__ float sX[CIN * 128];    // 16 KB

    int b  = blockIdx.x >> 11;             // 2048 tiles per batch
    int p0 = (blockIdx.x & 2047) << 7;     // tile start
    int t  = threadIdx.x;

    for (int i = t; i < CIN * RANK; i += 256) sW[i] = Win[i];
    for (int i = t; i < CIN * 128; i += 256) {
        int c = i >> 7, j = i & 127;
        sX[i] = x[(size_t)(b * CIN + c) * PVOL + p0 + j];
    }
    __syncthreads();

    int tp = t & 31;          // position lane 0..31
    int tr = t >> 5;          // rank group 0..7
    int r0 = tr * 8;

    float acc[8][4];
    #pragma unroll
    for (int i = 0; i < 8; i++)
        #pragma unroll
        for (int j = 0; j < 4; j++) acc[i][j] = 0.0f;

    #pragma unroll
    for (int c = 0; c < CIN; c++) {
        float xv[4], wv[8];
        #pragma unroll
        for (int j = 0; j < 4; j++) xv[j] = sX[c * 128 + tp + 32 * j];
        #pragma unroll
        for (int i = 0; i < 8; i++) wv[i] = sW[c * RANK + r0 + i];
        #pragma unroll
        for (int i = 0; i < 8; i++)
            #pragma unroll
            for (int j = 0; j < 4; j++) acc[i][j] += wv[i] * xv[j];
    }

    #pragma unroll
    for (int i = 0; i < 8; i++) {
        size_t base = (size_t)(b * RANK + r0 + i) * PVOL + p0 + tp;
        #pragma unroll
        for (int j = 0; j < 4; j++) g_bufA[base + 32 * j] = acc[i][j];
    }
}

// ---------------------------------------------------------------------------
// K2: h-tap.  t2[b,r,h,w,d] = sum_k y[b,r,h+k-1,w,d] * Uh[k,r]  (zero beyond)
// One thread per element; h-stride is 4096 elements.
// ---------------------------------------------------------------------------
__global__ void __launch_bounds__(256) k2_htap(const float* __restrict__ Uh) {
    int idx = blockIdx.x * 256 + threadIdx.x;   // < 2^25, fits int
    int r = (idx >> 18) & 63;
    int h = (idx >> 12) & 63;

    float u0 = __ldg(&Uh[r]);
    float u1 = __ldg(&Uh[64 + r]);
    float u2 = __ldg(&Uh[128 + r]);

    float s = u1 * __ldg(&g_bufA[idx]);
    if (h > 0)  s += u0 * __ldg(&g_bufA[idx - 4096]);
    if (h < 63) s += u2 * __ldg(&g_bufA[idx + 4096]);
    g_bufB[idx] = s;
}

// ---------------------------------------------------------------------------
// K3: fused w-tap + d-tap. One block per (b, r, h) plane (64x64) in smem.
// ---------------------------------------------------------------------------
__global__ void __launch_bounds__(256) k3_wdtap(const float* __restrict__ Uw,
                                                const float* __restrict__ Ud) {
    __shared__ float ps[64 * 65];
    __shared__ float qs[64 * 65];

    int blk = blockIdx.x;        // SB*RANK*S = 8192 blocks
    int h = blk & 63;
    int r = (blk >> 6) & 63;
    int b = blk >> 12;
    size_t base = ((size_t)(b * RANK + r) * S + h) * (size_t)(S * S);
    int t = threadIdx.x;

    float uw0 = __ldg(&Uw[r]), uw1 = __ldg(&Uw[64 + r]), uw2 = __ldg(&Uw[128 + r]);
    float ud0 = __ldg(&Ud[r]), ud1 = __ldg(&Ud[64 + r]), ud2 = __ldg(&Ud[128 + r]);

    #pragma unroll
    for (int i = 0; i < 16; i++) {
        int e = t + i * 256;
        int w = e >> 6, d = e & 63;
        ps[w * 65 + d] = __ldg(&g_bufB[base + e]);
    }
    __syncthreads();

    #pragma unroll
    for (int i = 0; i < 16; i++) {
        int e = t + i * 256;
        int w = e >> 6, d = e & 63;
        float s = uw1 * ps[w * 65 + d];
        if (w > 0)  s += uw0 * ps[(w - 1) * 65 + d];
        if (w < 63) s += uw2 * ps[(w + 1) * 65 + d];
        qs[w * 65 + d] = s;
    }
    __syncthreads();

    #pragma unroll
    for (int i = 0; i < 16; i++) {
        int e = t + i * 256;
        int w = e >> 6, d = e & 63;
        float s = ud1 * qs[w * 65 + d];
        if (d > 0)  s += ud0 * qs[w * 65 + d - 1];
        if (d < 63) s += ud2 * qs[w * 65 + d + 1];
        g_bufA[base + e] = s;
    }
}

// ---------------------------------------------------------------------------
// K4: projection  out[b,co,p] = sum_r t[b,r,p] * Uout[r,co] + bias[co]
// Block tile: 128 positions x 64 cout; all 64 rank-slices staged in smem.
// ---------------------------------------------------------------------------
__global__ void __launch_bounds__(256) k4_proj(const float* __restrict__ Uout,
                                               const float* __restrict__ bias,
                                               float* __restrict__ out) {
    __shared__ float sU[RANK * COUT];   // 16 KB
    __shared__ float sT[RANK * 128];    // 32 KB

    int b  = blockIdx.x >> 11;
    int p0 = (blockIdx.x & 2047) << 7;
    int t  = threadIdx.x;

    for (int i = t; i < RANK * COUT; i += 256) sU[i] = Uout[i];
    for (int i = t; i < RANK * 128; i += 256) {
        int r = i >> 7, j = i & 127;
        sT[i] = __ldg(&g_bufA[(size_t)(b * RANK + r) * PVOL + p0 + j]);
    }
    __syncthreads();

    int tp = t & 31;
    int tc = t >> 5;
    int c0 = tc * 8;

    float acc[8][4];
    #pragma unroll
    for (int i = 0; i < 8; i++)
        #pragma unroll
        for (int j = 0; j < 4; j++) acc[i][j] = 0.0f;

    #pragma unroll 16
    for (int r = 0; r < RANK; r++) {
        float xv[4], wv[8];
        #pragma unroll
        for (int j = 0; j < 4; j++) xv[j] = sT[r * 128 + tp + 32 * j];
        #pragma unroll
        for (int i = 0; i < 8; i++) wv[i] = sU[r * COUT + c0 + i];
        #pragma unroll
        for (int i = 0; i < 8; i++)
            #pragma unroll
            for (int j = 0; j < 4; j++) acc[i][j] += wv[i] * xv[j];
    }

    #pragma unroll
    for (int i = 0; i < 8; i++) {
        float bv = __ldg(&bias[c0 + i]);
        size_t base = (size_t)(b * COUT + c0 + i) * PVOL + p0 + tp;
        #pragma unroll
        for (int j = 0; j < 4; j++) out[base + 32 * j] = acc[i][j] + bv;
    }
}

// ---------------------------------------------------------------------------
extern "C" void kernel_launch(void* const* d_in, const int* in_sizes, int n_in,
                              void* d_out, int out_size) {
    const float* x    = (const float*)d_in[0];
    const float* Uh   = (const float*)d_in[1];
    const float* Uw   = (const float*)d_in[2];
    const float* Ud   = (const float*)d_in[3];
    const float* Win  = (const float*)d_in[4];
    const float* Uout = (const float*)d_in[5];
    const float* bias = (const float*)d_in[6];
    float* out = (float*)d_out;

    k1_chan<<<SB * (PVOL / 128), 256>>>(x, Win);
    k2_htap<<<(SB * RANK * PVOL) / 256, 256>>>(Uh);
    k3_wdtap<<<SB * RANK * S, 256>>>(Uw, Ud);
    k4_proj<<<SB * (PVOL / 128), 256>>>(Uout, bias, out);
}

// round 2
// speedup vs baseline: 2.1595x; 2.1595x over previous
#include <cuda_runtime.h>

#define SB   2
#define CIN  32
#define COUT 64
#define RANK 64
#define S    64
#define PVOL (S*S*S)   // 262144

// Scratch (alloc-free rule: device globals). 134 MB each.
__device__ float g_bufA[(size_t)SB * RANK * PVOL];
__device__ float g_bufB[(size_t)SB * RANK * PVOL];

// ---------------------------------------------------------------------------
// K1: channel contraction  y[b,r,p] = sum_c x[b,c,p] * Win[c,r]
// Block: 128 positions x 64 ranks. Thread: 8 ranks x 4 contiguous positions.
// ---------------------------------------------------------------------------
__global__ void __launch_bounds__(256) k1_chan(const float* __restrict__ x,
                                               const float* __restrict__ Win) {
    __shared__ float sW[CIN * RANK];   // 8 KB
    __shared__ float sX[CIN * 128];    // 16 KB

    int b  = blockIdx.x >> 11;
    int p0 = (blockIdx.x & 2047) << 7;
    int t  = threadIdx.x;

    #pragma unroll
    for (int i = t; i < CIN * RANK / 4; i += 256)
        ((float4*)sW)[i] = ((const float4*)Win)[i];

    const float4* x4 = (const float4*)(x + (size_t)b * CIN * PVOL + p0);
    #pragma unroll
    for (int i = t; i < CIN * 32; i += 256) {
        int c = i >> 5, j = i & 31;
        ((float4*)sX)[c * 32 + j] = x4[(size_t)c * (PVOL / 4) + j];
    }
    __syncthreads();

    int tp = t & 31;
    int r0 = (t >> 5) * 8;

    float acc[8][4];
    #pragma unroll
    for (int i = 0; i < 8; i++)
        #pragma unroll
        for (int j = 0; j < 4; j++) acc[i][j] = 0.0f;

    #pragma unroll
    for (int c = 0; c < CIN; c++) {
        float4 xv = ((float4*)sX)[c * 32 + tp];
        float4 w0 = ((float4*)sW)[(c * RANK + r0) >> 2];
        float4 w1 = ((float4*)sW)[((c * RANK + r0) >> 2) + 1];
        float wv[8] = {w0.x, w0.y, w0.z, w0.w, w1.x, w1.y, w1.z, w1.w};
        #pragma unroll
        for (int i = 0; i < 8; i++) {
            acc[i][0] += wv[i] * xv.x;
            acc[i][1] += wv[i] * xv.y;
            acc[i][2] += wv[i] * xv.z;
            acc[i][3] += wv[i] * xv.w;
        }
    }

    #pragma unroll
    for (int i = 0; i < 8; i++) {
        float4 o = make_float4(acc[i][0], acc[i][1], acc[i][2], acc[i][3]);
        *(float4*)(g_bufA + (size_t)(b * RANK + r0 + i) * PVOL + p0 + tp * 4) = o;
    }
}

// ---------------------------------------------------------------------------
// K23: fused h-tap + w-tap + d-tap.
// One block per output (b,r,h) plane. Reads planes h-1,h,h+1 of g_bufA from
// gmem (L2 reuse: consecutive blocks share planes), pipes through smem.
// ---------------------------------------------------------------------------
__global__ void __launch_bounds__(256) k23_taps(const float* __restrict__ Uh,
                                                const float* __restrict__ Uw,
                                                const float* __restrict__ Ud) {
    __shared__ float hq[64 * 68];   // 17.4 KB (pad 4 keeps float4 alignment)
    __shared__ float qs[64 * 68];

    int blk = blockIdx.x;            // SB*RANK*S = 8192 blocks, h fastest
    int h = blk & 63;
    int r = (blk >> 6) & 63;
    int b = blk >> 12;
    size_t base = ((size_t)(b * RANK + r) * S + h) * (size_t)(S * S);
    int t = threadIdx.x;

    float uh0 = __ldg(&Uh[r]), uh1 = __ldg(&Uh[64 + r]), uh2 = __ldg(&Uh[128 + r]);
    float uw0 = __ldg(&Uw[r]), uw1 = __ldg(&Uw[64 + r]), uw2 = __ldg(&Uw[128 + r]);
    float ud0 = __ldg(&Ud[r]), ud1 = __ldg(&Ud[64 + r]), ud2 = __ldg(&Ud[128 + r]);

    const float4* A0 = (const float4*)(g_bufA + base);   // plane stride = 1024 float4

    // h-tap into hq
    #pragma unroll
    for (int i = 0; i < 4; i++) {
        int q = t + i * 256;          // float4 index within plane, 0..1023
        int w = q >> 4, d4 = q & 15;
        float4 v0 = __ldg(&A0[q]);
        float4 vm = make_float4(0.f, 0.f, 0.f, 0.f);
        float4 vp = make_float4(0.f, 0.f, 0.f, 0.f);
        if (h > 0)  vm = __ldg(&A0[q - 1024]);
        if (h < 63) vp = __ldg(&A0[q + 1024]);
        float4 o;
        o.x = uh0 * vm.x + uh1 * v0.x + uh2 * vp.x;
        o.y = uh0 * vm.y + uh1 * v0.y + uh2 * vp.y;
        o.z = uh0 * vm.z + uh1 * v0.z + uh2 * vp.z;
        o.w = uh0 * vm.w + uh1 * v0.w + uh2 * vp.w;
        *(float4*)&hq[w * 68 + d4 * 4] = o;
    }
    __syncthreads();

    // w-tap into qs
    #pragma unroll
    for (int i = 0; i < 4; i++) {
        int q = t + i * 256;
        int w = q >> 4, d4 = q & 15;
        float4 c0 = *(const float4*)&hq[w * 68 + d4 * 4];
        float4 m  = make_float4(0.f, 0.f, 0.f, 0.f);
        float4 p  = make_float4(0.f, 0.f, 0.f, 0.f);
        if (w > 0)  m = *(const float4*)&hq[(w - 1) * 68 + d4 * 4];
        if (w < 63) p = *(const float4*)&hq[(w + 1) * 68 + d4 * 4];
        float4 o;
        o.x = uw0 * m.x + uw1 * c0.x + uw2 * p.x;
        o.y = uw0 * m.y + uw1 * c0.y + uw2 * p.y;
        o.z = uw0 * m.z + uw1 * c0.z + uw2 * p.z;
        o.w = uw0 * m.w + uw1 * c0.w + uw2 * p.w;
        *(float4*)&qs[w * 68 + d4 * 4] = o;
    }
    __syncthreads();

    // d-tap, write to gmem
    float4* Bo = (float4*)(g_bufB + base);
    #pragma unroll
    for (int i = 0; i < 4; i++) {
        int q = t + i * 256;
        int w = q >> 4, d4 = q & 15;
        int d = d4 * 4;
        const float* row = &qs[w * 68];
        float a0 = row[d], a1 = row[d + 1], a2 = row[d + 2], a3 = row[d + 3];
        float lft = (d > 0)      ? row[d - 1] : 0.f;
        float rgt = (d + 4 < 64) ? row[d + 4] : 0.f;
        float4 o;
        o.x = ud0 * lft + ud1 * a0 + ud2 * a1;
        o.y = ud0 * a0  + ud1 * a1 + ud2 * a2;
        o.z = ud0 * a1  + ud1 * a2 + ud2 * a3;
        o.w = ud0 * a2  + ud1 * a3 + ud2 * rgt;
        Bo[q] = o;
    }
}

// ---------------------------------------------------------------------------
// K4: projection  out[b,co,p] = sum_r t[b,r,p] * Uout[r,co] + bias[co]
// Block: 128 positions x 64 couts. Thread: 8 couts x 4 contiguous positions.
// ---------------------------------------------------------------------------
__global__ void __launch_bounds__(256) k4_proj(const float* __restrict__ Uout,
                                               const float* __restrict__ bias,
                                               float* __restrict__ out) {
    __shared__ float sU[RANK * COUT];   // 16 KB
    __shared__ float sT[RANK * 128];    // 32 KB

    int b  = blockIdx.x >> 11;
    int p0 = (blockIdx.x & 2047) << 7;
    int t  = threadIdx.x;

    #pragma unroll
    for (int i = t; i < RANK * COUT / 4; i += 256)
        ((float4*)sU)[i] = ((const float4*)Uout)[i];

    const float4* T4 = (const float4*)(g_bufB + (size_t)b * RANK * PVOL + p0);
    #pragma unroll
    for (int i = t; i < RANK * 32; i += 256) {
        int rr = i >> 5, j = i & 31;
        ((float4*)sT)[rr * 32 + j] = T4[(size_t)rr * (PVOL / 4) + j];
    }
    __syncthreads();

    int tp = t & 31;
    int c0 = (t >> 5) * 8;

    float acc[8][4];
    #pragma unroll
    for (int i = 0; i < 8; i++)
        #pragma unroll
        for (int j = 0; j < 4; j++) acc[i][j] = 0.0f;

    #pragma unroll 8
    for (int r = 0; r < RANK; r++) {
        float4 xv = ((float4*)sT)[r * 32 + tp];
        float4 w0 = ((float4*)sU)[(r * COUT + c0) >> 2];
        float4 w1 = ((float4*)sU)[((r * COUT + c0) >> 2) + 1];
        float wv[8] = {w0.x, w0.y, w0.z, w0.w, w1.x, w1.y, w1.z, w1.w};
        #pragma unroll
        for (int i = 0; i < 8; i++) {
            acc[i][0] += wv[i] * xv.x;
            acc[i][1] += wv[i] * xv.y;
            acc[i][2] += wv[i] * xv.z;
            acc[i][3] += wv[i] * xv.w;
        }
    }

    #pragma unroll
    for (int i = 0; i < 8; i++) {
        float bv = __ldg(&bias[c0 + i]);
        float4 o = make_float4(acc[i][0] + bv, acc[i][1] + bv,
                               acc[i][2] + bv, acc[i][3] + bv);
        *(float4*)(out + (size_t)(b * COUT + c0 + i) * PVOL + p0 + tp * 4) = o;
    }
}

// ---------------------------------------------------------------------------
extern "C" void kernel_launch(void* const* d_in, const int* in_sizes, int n_in,
                              void* d_out, int out_size) {
    const float* x    = (const float*)d_in[0];
    const float* Uh   = (const float*)d_in[1];
    const float* Uw   = (const float*)d_in[2];
    const float* Ud   = (const float*)d_in[3];
    const float* Win  = (const float*)d_in[4];
    const float* Uout = (const float*)d_in[5];
    const float* bias = (const float*)d_in[6];
    float* out = (float*)d_out;

    k1_chan<<<SB * (PVOL / 128), 256>>>(x, Win);
    k23_taps<<<SB * RANK * S, 256>>>(Uh, Uw, Ud);
    k4_proj<<<SB * (PVOL / 128), 256>>>(Uout, bias, out);
}

// round 3
// speedup vs baseline: 2.6592x; 1.2314x over previous
#include <cuda_runtime.h>

#define SB   2
#define CIN  32
#define COUT 64
#define RANK 64
#define S    64
#define PVOL (S*S*S)   // 262144

// Scratch (alloc-free rule: device globals). 134 MB each.
__device__ float g_bufA[(size_t)SB * RANK * PVOL];
__device__ float g_bufB[(size_t)SB * RANK * PVOL];

// ---------------------------------------------------------------------------
// tf32 helpers
// ---------------------------------------------------------------------------
__device__ __forceinline__ unsigned f2tf(float f) {
    unsigned u;
    asm("cvt.rna.tf32.f32 %0, %1;" : "=r"(u) : "f"(f));
    return u;
}

__device__ __forceinline__ void mma_tf32(float c[4], const unsigned a[4],
                                         const unsigned b0, const unsigned b1) {
    asm volatile(
        "mma.sync.aligned.m16n8k8.row.col.f32.tf32.tf32.f32 "
        "{%0,%1,%2,%3}, {%4,%5,%6,%7}, {%8,%9}, {%0,%1,%2,%3};"
        : "+f"(c[0]), "+f"(c[1]), "+f"(c[2]), "+f"(c[3])
        : "r"(a[0]), "r"(a[1]), "r"(a[2]), "r"(a[3]), "r"(b0), "r"(b1));
}

// ---------------------------------------------------------------------------
// K1 (tensor): y[b,r,p] = sum_c Win[c,r] * x[b,c,p]
// GEMM: D[M=r, N=p] = A[r,c] * B[c,p].  A = Win^T (weights, registers),
// B = x tile in natural [c][p] smem layout. Block: 64 r x 128 p. 8 warps,
// warp tile 16 r x 64 p.
// ---------------------------------------------------------------------------
__global__ void __launch_bounds__(256) k1_mma(const float* __restrict__ x,
                                              const float* __restrict__ Win) {
    __shared__ unsigned sW[CIN * 72];    // Win natural [c][r], ld=72, tf32
    __shared__ unsigned sX[CIN * 136];   // x tile [c][p], ld=136, tf32

    int b  = blockIdx.x >> 11;
    int p0 = (blockIdx.x & 2047) << 7;
    int t  = threadIdx.x;

    // fill sW: Win is [c][r] row-major (32x64)
    {
        const float4* W4 = (const float4*)Win;
        for (int i = t; i < CIN * RANK / 4; i += 256) {
            int c = i >> 4, r4 = i & 15;
            float4 v = W4[i];
            unsigned* dst = &sW[c * 72 + 4 * r4];
            dst[0] = f2tf(v.x); dst[1] = f2tf(v.y);
            dst[2] = f2tf(v.z); dst[3] = f2tf(v.w);
        }
    }
    // fill sX: x[b,c,p0..p0+127]
    {
        const float4* x4 = (const float4*)(x + (size_t)b * CIN * PVOL + p0);
        #pragma unroll
        for (int i = t; i < CIN * 32; i += 256) {
            int c = i >> 5, j = i & 31;
            float4 v = __ldg(&x4[(size_t)c * (PVOL / 4) + j]);
            uint4 u = make_uint4(f2tf(v.x), f2tf(v.y), f2tf(v.z), f2tf(v.w));
            *(uint4*)&sX[c * 136 + 4 * j] = u;
        }
    }
    __syncthreads();

    int lane = t & 31, wid = t >> 5;
    int g = lane >> 2, tg = lane & 3;
    int r0 = (wid >> 1) * 16;       // M offset (rank)
    int pW = (wid & 1) * 64;        // N offset (position half)

    // preload A fragments: A[row=r][col=c] = Win[c][r]
    unsigned A[4][4];
    #pragma unroll
    for (int ks = 0; ks < 4; ks++) {
        A[ks][0] = sW[(ks * 8 + tg) * 72 + r0 + g];
        A[ks][1] = sW[(ks * 8 + tg) * 72 + r0 + g + 8];
        A[ks][2] = sW[(ks * 8 + tg + 4) * 72 + r0 + g];
        A[ks][3] = sW[(ks * 8 + tg + 4) * 72 + r0 + g + 8];
    }

    float C[8][4];
    #pragma unroll
    for (int ni = 0; ni < 8; ni++)
        #pragma unroll
        for (int j = 0; j < 4; j++) C[ni][j] = 0.0f;

    #pragma unroll
    for (int ks = 0; ks < 4; ks++) {
        #pragma unroll
        for (int ni = 0; ni < 8; ni++) {
            unsigned b0 = sX[(ks * 8 + tg) * 136 + pW + 8 * ni + g];
            unsigned b1 = sX[(ks * 8 + tg + 4) * 136 + pW + 8 * ni + g];
            mma_tf32(C[ni], A[ks], b0, b1);
        }
    }

    // epilogue: D[r, p] -> g_bufA[b, r, p]
    #pragma unroll
    for (int ni = 0; ni < 8; ni++) {
        int p = p0 + pW + 8 * ni + 2 * tg;
        size_t o0 = (size_t)(b * RANK + r0 + g) * PVOL + p;
        size_t o1 = (size_t)(b * RANK + r0 + g + 8) * PVOL + p;
        *(float2*)&g_bufA[o0] = make_float2(C[ni][0], C[ni][1]);
        *(float2*)&g_bufA[o1] = make_float2(C[ni][2], C[ni][3]);
    }
}

// ---------------------------------------------------------------------------
// K23: fused h-tap + w-tap + d-tap (fp32, memory-bound).
// One block per output (b,r,h) plane.
// ---------------------------------------------------------------------------
__global__ void __launch_bounds__(256) k23_taps(const float* __restrict__ Uh,
                                                const float* __restrict__ Uw,
                                                const float* __restrict__ Ud) {
    __shared__ float hq[64 * 68];
    __shared__ float qs[64 * 68];

    int blk = blockIdx.x;
    int h = blk & 63;
    int r = (blk >> 6) & 63;
    int b = blk >> 12;
    size_t base = ((size_t)(b * RANK + r) * S + h) * (size_t)(S * S);
    int t = threadIdx.x;

    float uh0 = __ldg(&Uh[r]), uh1 = __ldg(&Uh[64 + r]), uh2 = __ldg(&Uh[128 + r]);
    float uw0 = __ldg(&Uw[r]), uw1 = __ldg(&Uw[64 + r]), uw2 = __ldg(&Uw[128 + r]);
    float ud0 = __ldg(&Ud[r]), ud1 = __ldg(&Ud[64 + r]), ud2 = __ldg(&Ud[128 + r]);

    const float4* A0 = (const float4*)(g_bufA + base);

    #pragma unroll
    for (int i = 0; i < 4; i++) {
        int q = t + i * 256;
        int w = q >> 4, d4 = q & 15;
        float4 v0 = __ldg(&A0[q]);
        float4 vm = make_float4(0.f, 0.f, 0.f, 0.f);
        float4 vp = make_float4(0.f, 0.f, 0.f, 0.f);
        if (h > 0)  vm = __ldg(&A0[q - 1024]);
        if (h < 63) vp = __ldg(&A0[q + 1024]);
        float4 o;
        o.x = uh0 * vm.x + uh1 * v0.x + uh2 * vp.x;
        o.y = uh0 * vm.y + uh1 * v0.y + uh2 * vp.y;
        o.z = uh0 * vm.z + uh1 * v0.z + uh2 * vp.z;
        o.w = uh0 * vm.w + uh1 * v0.w + uh2 * vp.w;
        *(float4*)&hq[w * 68 + d4 * 4] = o;
    }
    __syncthreads();

    #pragma unroll
    for (int i = 0; i < 4; i++) {
        int q = t + i * 256;
        int w = q >> 4, d4 = q & 15;
        float4 c0 = *(const float4*)&hq[w * 68 + d4 * 4];
        float4 m  = make_float4(0.f, 0.f, 0.f, 0.f);
        float4 p  = make_float4(0.f, 0.f, 0.f, 0.f);
        if (w > 0)  m = *(const float4*)&hq[(w - 1) * 68 + d4 * 4];
        if (w < 63) p = *(const float4*)&hq[(w + 1) * 68 + d4 * 4];
        float4 o;
        o.x = uw0 * m.x + uw1 * c0.x + uw2 * p.x;
        o.y = uw0 * m.y + uw1 * c0.y + uw2 * p.y;
        o.z = uw0 * m.z + uw1 * c0.z + uw2 * p.z;
        o.w = uw0 * m.w + uw1 * c0.w + uw2 * p.w;
        *(float4*)&qs[w * 68 + d4 * 4] = o;
    }
    __syncthreads();

    float4* Bo = (float4*)(g_bufB + base);
    #pragma unroll
    for (int i = 0; i < 4; i++) {
        int q = t + i * 256;
        int w = q >> 4, d4 = q & 15;
        int d = d4 * 4;
        const float* row = &qs[w * 68];
        float a0 = row[d], a1 = row[d + 1], a2 = row[d + 2], a3 = row[d + 3];
        float lft = (d > 0)      ? row[d - 1] : 0.f;
        float rgt = (d + 4 < 64) ? row[d + 4] : 0.f;
        float4 o;
        o.x = ud0 * lft + ud1 * a0 + ud2 * a1;
        o.y = ud0 * a0  + ud1 * a1 + ud2 * a2;
        o.z = ud0 * a1  + ud1 * a2 + ud2 * a3;
        o.w = ud0 * a2  + ud1 * a3 + ud2 * rgt;
        Bo[q] = o;
    }
}

// ---------------------------------------------------------------------------
// K4 (tensor): out[b,co,p] = sum_r Uout[r,co] * t[b,r,p] + bias[co]
// GEMM: D[M=co, N=p] = A[co,r] * B[r,p].  A = Uout^T (registers),
// B = t tile natural [r][p].  Block: 64 co x 128 p.  Dynamic smem 52 KB.
// ---------------------------------------------------------------------------
__global__ void __launch_bounds__(256) k4_mma(const float* __restrict__ Uout,
                                              const float* __restrict__ bias,
                                              float* __restrict__ out) {
    extern __shared__ unsigned dsm[];
    unsigned* sU = dsm;                 // Uout natural [r][co], ld=72, tf32
    unsigned* sT = dsm + RANK * 72;     // t tile [r][p], ld=136, tf32

    int b  = blockIdx.x >> 11;
    int p0 = (blockIdx.x & 2047) << 7;
    int t  = threadIdx.x;

    {
        const float4* U4 = (const float4*)Uout;   // [r][co] 64x64
        for (int i = t; i < RANK * COUT / 4; i += 256) {
            int r = i >> 4, c4 = i & 15;
            float4 v = U4[i];
            unsigned* dst = &sU[r * 72 + 4 * c4];
            dst[0] = f2tf(v.x); dst[1] = f2tf(v.y);
            dst[2] = f2tf(v.z); dst[3] = f2tf(v.w);
        }
    }
    {
        const float4* T4 = (const float4*)(g_bufB + (size_t)b * RANK * PVOL + p0);
        #pragma unroll
        for (int i = t; i < RANK * 32; i += 256) {
            int r = i >> 5, j = i & 31;
            float4 v = __ldg(&T4[(size_t)r * (PVOL / 4) + j]);
            uint4 u = make_uint4(f2tf(v.x), f2tf(v.y), f2tf(v.z), f2tf(v.w));
            *(uint4*)&sT[r * 136 + 4 * j] = u;
        }
    }
    __syncthreads();

    int lane = t & 31, wid = t >> 5;
    int g = lane >> 2, tg = lane & 3;
    int c0 = (wid >> 1) * 16;       // M offset (cout)
    int pW = (wid & 1) * 64;        // N offset

    unsigned A[8][4];
    #pragma unroll
    for (int ks = 0; ks < 8; ks++) {
        A[ks][0] = sU[(ks * 8 + tg) * 72 + c0 + g];
        A[ks][1] = sU[(ks * 8 + tg) * 72 + c0 + g + 8];
        A[ks][2] = sU[(ks * 8 + tg + 4) * 72 + c0 + g];
        A[ks][3] = sU[(ks * 8 + tg + 4) * 72 + c0 + g + 8];
    }

    float C[8][4];
    #pragma unroll
    for (int ni = 0; ni < 8; ni++)
        #pragma unroll
        for (int j = 0; j < 4; j++) C[ni][j] = 0.0f;

    #pragma unroll
    for (int ks = 0; ks < 8; ks++) {
        #pragma unroll
        for (int ni = 0; ni < 8; ni++) {
            unsigned b0 = sT[(ks * 8 + tg) * 136 + pW + 8 * ni + g];
            unsigned b1 = sT[(ks * 8 + tg + 4) * 136 + pW + 8 * ni + g];
            mma_tf32(C[ni], A[ks], b0, b1);
        }
    }

    float bv0 = __ldg(&bias[c0 + g]);        // row co0+g   (c0,c1)
    float bv1 = __ldg(&bias[c0 + g + 8]);    // row co0+g+8 (c2,c3)
    #pragma unroll
    for (int ni = 0; ni < 8; ni++) {
        int p = p0 + pW + 8 * ni + 2 * tg;
        size_t o0 = (size_t)(b * COUT + c0 + g) * PVOL + p;
        size_t o1 = (size_t)(b * COUT + c0 + g + 8) * PVOL + p;
        *(float2*)&out[o0] = make_float2(C[ni][0] + bv0, C[ni][1] + bv0);
        *(float2*)&out[o1] = make_float2(C[ni][2] + bv1, C[ni][3] + bv1);
    }
}

// ---------------------------------------------------------------------------
extern "C" void kernel_launch(void* const* d_in, const int* in_sizes, int n_in,
                              void* d_out, int out_size) {
    const float* x    = (const float*)d_in[0];
    const float* Uh   = (const float*)d_in[1];
    const float* Uw   = (const float*)d_in[2];
    const float* Ud   = (const float*)d_in[3];
    const float* Win  = (const float*)d_in[4];
    const float* Uout = (const float*)d_in[5];
    const float* bias = (const float*)d_in[6];
    float* out = (float*)d_out;

    const int k4_smem = (RANK * 72 + RANK * 136) * 4;   // 53248 bytes
    cudaFuncSetAttribute(k4_mma, cudaFuncAttributeMaxDynamicSharedMemorySize,
                         k4_smem);

    k1_mma<<<SB * (PVOL / 128), 256>>>(x, Win);
    k23_taps<<<SB * RANK * S, 256>>>(Uh, Uw, Ud);
    k4_mma<<<SB * (PVOL / 128), 256, k4_smem>>>(Uout, bias, out);
}

// round 4
// speedup vs baseline: 2.6832x; 1.0090x over previous
#include <cuda_runtime.h>

#define SB   2
#define CIN  32
#define COUT 64
#define RANK 64
#define S    64
#define PVOL (S*S*S)   // 262144

// Scratch (alloc-free rule: device globals). 134 MB each.
__device__ float g_bufA[(size_t)SB * RANK * PVOL];
__device__ float g_bufB[(size_t)SB * RANK * PVOL];

// ---------------------------------------------------------------------------
// tf32 helpers
// ---------------------------------------------------------------------------
__device__ __forceinline__ unsigned f2tf(float f) {
    unsigned u;
    asm("cvt.rna.tf32.f32 %0, %1;" : "=r"(u) : "f"(f));
    return u;
}

__device__ __forceinline__ void mma_tf32(float c[4], const unsigned a[4],
                                         const unsigned b0, const unsigned b1) {
    asm volatile(
        "mma.sync.aligned.m16n8k8.row.col.f32.tf32.tf32.f32 "
        "{%0,%1,%2,%3}, {%4,%5,%6,%7}, {%8,%9}, {%0,%1,%2,%3};"
        : "+f"(c[0]), "+f"(c[1]), "+f"(c[2]), "+f"(c[3])
        : "r"(a[0]), "r"(a[1]), "r"(a[2]), "r"(a[3]), "r"(b0), "r"(b1));
}

// ---------------------------------------------------------------------------
// K1 (tensor, pipelined): y[b,r,p] = sum_c Win[c,r] * x[b,c,p]
// Block handles 4 consecutive 128-p tiles. Register-staged prefetch of the
// next tile overlaps the mma loop of the current tile.
// ---------------------------------------------------------------------------
__global__ void __launch_bounds__(256) k1_mma(const float* __restrict__ x,
                                              const float* __restrict__ Win) {
    __shared__ unsigned sW[CIN * 72];    // Win natural [c][r], ld=72, tf32
    __shared__ unsigned sX[CIN * 136];   // x tile [c][p], ld=136, tf32

    int b      = blockIdx.x >> 9;
    int p_base = (blockIdx.x & 511) << 9;   // 4 tiles x 128
    int t      = threadIdx.x;

    // fill sW
    {
        const float4* W4 = (const float4*)Win;
        for (int i = t; i < CIN * RANK / 4; i += 256) {
            int c = i >> 4, r4 = i & 15;
            float4 v = W4[i];
            unsigned* dst = &sW[c * 72 + 4 * r4];
            dst[0] = f2tf(v.x); dst[1] = f2tf(v.y);
            dst[2] = f2tf(v.z); dst[3] = f2tf(v.w);
        }
    }

    const float4* x4 = (const float4*)(x + (size_t)b * CIN * PVOL);
    int j  = t & 31;       // f4 index within 128-p tile
    int c0 = t >> 5;       // channel rows c0 + 8s

    // stage tile 0
    float4 stg[4];
    #pragma unroll
    for (int s = 0; s < 4; s++)
        stg[s] = __ldg(&x4[(size_t)(c0 + 8 * s) * (PVOL / 4) + (p_base >> 2) + j]);
    #pragma unroll
    for (int s = 0; s < 4; s++) {
        uint4 u = make_uint4(f2tf(stg[s].x), f2tf(stg[s].y),
                             f2tf(stg[s].z), f2tf(stg[s].w));
        *(uint4*)&sX[(c0 + 8 * s) * 136 + 4 * j] = u;
    }
    __syncthreads();

    int lane = t & 31, wid = t >> 5;
    int g = lane >> 2, tg = lane & 3;
    int r0 = (wid >> 1) * 16;
    int pW = (wid & 1) * 64;

    // preload A fragments once
    unsigned A[4][4];
    #pragma unroll
    for (int ks = 0; ks < 4; ks++) {
        A[ks][0] = sW[(ks * 8 + tg) * 72 + r0 + g];
        A[ks][1] = sW[(ks * 8 + tg) * 72 + r0 + g + 8];
        A[ks][2] = sW[(ks * 8 + tg + 4) * 72 + r0 + g];
        A[ks][3] = sW[(ks * 8 + tg + 4) * 72 + r0 + g + 8];
    }

    #pragma unroll
    for (int tt = 0; tt < 4; tt++) {
        int p0 = p_base + tt * 128;

        // prefetch next tile into registers (overlaps mma below)
        if (tt < 3) {
            #pragma unroll
            for (int s = 0; s < 4; s++)
                stg[s] = __ldg(&x4[(size_t)(c0 + 8 * s) * (PVOL / 4)
                                   + ((p0 + 128) >> 2) + j]);
        }

        float C[8][4];
        #pragma unroll
        for (int ni = 0; ni < 8; ni++)
            #pragma unroll
            for (int q = 0; q < 4; q++) C[ni][q] = 0.0f;

        #pragma unroll
        for (int ks = 0; ks < 4; ks++) {
            #pragma unroll
            for (int ni = 0; ni < 8; ni++) {
                unsigned b0 = sX[(ks * 8 + tg) * 136 + pW + 8 * ni + g];
                unsigned b1 = sX[(ks * 8 + tg + 4) * 136 + pW + 8 * ni + g];
                mma_tf32(C[ni], A[ks], b0, b1);
            }
        }

        #pragma unroll
        for (int ni = 0; ni < 8; ni++) {
            int p = p0 + pW + 8 * ni + 2 * tg;
            size_t o0 = (size_t)(b * RANK + r0 + g) * PVOL + p;
            size_t o1 = (size_t)(b * RANK + r0 + g + 8) * PVOL + p;
            *(float2*)&g_bufA[o0] = make_float2(C[ni][0], C[ni][1]);
            *(float2*)&g_bufA[o1] = make_float2(C[ni][2], C[ni][3]);
        }

        if (tt < 3) {
            __syncthreads();   // everyone done reading sX
            #pragma unroll
            for (int s = 0; s < 4; s++) {
                uint4 u = make_uint4(f2tf(stg[s].x), f2tf(stg[s].y),
                                     f2tf(stg[s].z), f2tf(stg[s].w));
                *(uint4*)&sX[(c0 + 8 * s) * 136 + 4 * j] = u;
            }
            __syncthreads();   // sX ready
        }
    }
}

// ---------------------------------------------------------------------------
// K23 (streaming): fused h/w/d taps. Block owns (b, r, h-octet); raw planes
// stream through a 3-slot rolling smem buffer so each plane is read once.
// Dynamic smem: raw[3][4096] + hq[64*68] + qs[64*68] = 83968 bytes.
// ---------------------------------------------------------------------------
__global__ void __launch_bounds__(256) k23_stream(const float* __restrict__ Uh,
                                                  const float* __restrict__ Uw,
                                                  const float* __restrict__ Ud) {
    extern __shared__ float dsm[];
    float* raw = dsm;                  // 3 * 4096
    float* hq  = dsm + 3 * 4096;       // 64*68
    float* qs  = hq + 64 * 68;

    int blk = blockIdx.x;              // hc fastest
    int hc = blk & 7;
    int r  = (blk >> 3) & 63;
    int b  = blk >> 9;
    int h0 = hc * 8;
    size_t rbase = (size_t)(b * RANK + r) * PVOL;
    int t = threadIdx.x;

    float uh0 = __ldg(&Uh[r]), uh1 = __ldg(&Uh[64 + r]), uh2 = __ldg(&Uh[128 + r]);
    float uw0 = __ldg(&Uw[r]), uw1 = __ldg(&Uw[64 + r]), uw2 = __ldg(&Uw[128 + r]);
    float ud0 = __ldg(&Ud[r]), ud1 = __ldg(&Ud[64 + r]), ud2 = __ldg(&Ud[128 + r]);

    const float4 z4 = make_float4(0.f, 0.f, 0.f, 0.f);

    // prologue: planes h0-1, h0, h0+1 into slots (h%3)
    #pragma unroll
    for (int k = -1; k <= 1; k++) {
        int hp = h0 + k;
        int slot = (hp + 3) % 3;
        const float4* src = (const float4*)(g_bufA + rbase + (size_t)hp * 4096);
        #pragma unroll
        for (int i = 0; i < 4; i++) {
            int q = t + i * 256;
            float4 v = (hp >= 0 && hp < 64) ? __ldg(&src[q]) : z4;
            *(float4*)&raw[slot * 4096 + q * 4] = v;
        }
    }
    __syncthreads();

    for (int hh = 0; hh < 8; hh++) {
        int h = h0 + hh;
        int sm_ = (h + 2) % 3;     // h-1
        int s0  = h % 3;
        int sp  = (h + 1) % 3;

        // h-tap: raw -> hq
        #pragma unroll
        for (int i = 0; i < 4; i++) {
            int q = t + i * 256;
            int w = q >> 4, d4 = q & 15;
            float4 vm = *(const float4*)&raw[sm_ * 4096 + q * 4];
            float4 v0 = *(const float4*)&raw[s0 * 4096 + q * 4];
            float4 vp = *(const float4*)&raw[sp * 4096 + q * 4];
            float4 o;
            o.x = uh0 * vm.x + uh1 * v0.x + uh2 * vp.x;
            o.y = uh0 * vm.y + uh1 * v0.y + uh2 * vp.y;
            o.z = uh0 * vm.z + uh1 * v0.z + uh2 * vp.z;
            o.w = uh0 * vm.w + uh1 * v0.w + uh2 * vp.w;
            *(float4*)&hq[w * 68 + d4 * 4] = o;
        }
        __syncthreads();   // hq ready; raw[sm_] now free

        // prefetch plane h+2 into registers (overlaps w/d taps)
        float4 stg[4];
        int hn = h + 2;
        if (hh < 7) {
            const float4* src = (const float4*)(g_bufA + rbase + (size_t)hn * 4096);
            #pragma unroll
            for (int i = 0; i < 4; i++) {
                int q = t + i * 256;
                stg[i] = (hn < 64) ? __ldg(&src[q]) : z4;
            }
        }

        // w-tap: hq -> qs
        #pragma unroll
        for (int i = 0; i < 4; i++) {
            int q = t + i * 256;
            int w = q >> 4, d4 = q & 15;
            float4 c0 = *(const float4*)&hq[w * 68 + d4 * 4];
            float4 m = z4, p = z4;
            if (w > 0)  m = *(const float4*)&hq[(w - 1) * 68 + d4 * 4];
            if (w < 63) p = *(const float4*)&hq[(w + 1) * 68 + d4 * 4];
            float4 o;
            o.x = uw0 * m.x + uw1 * c0.x + uw2 * p.x;
            o.y = uw0 * m.y + uw1 * c0.y + uw2 * p.y;
            o.z = uw0 * m.z + uw1 * c0.z + uw2 * p.z;
            o.w = uw0 * m.w + uw1 * c0.w + uw2 * p.w;
            *(float4*)&qs[w * 68 + d4 * 4] = o;
        }
        __syncthreads();   // qs ready

        // d-tap: qs -> gmem
        float4* Bo = (float4*)(g_bufB + rbase + (size_t)h * 4096);
        #pragma unroll
        for (int i = 0; i < 4; i++) {
            int q = t + i * 256;
            int w = q >> 4, d4 = q & 15;
            int d = d4 * 4;
            const float* row = &qs[w * 68];
            float a0 = row[d], a1 = row[d + 1], a2 = row[d + 2], a3 = row[d + 3];
            float lft = (d > 0)      ? row[d - 1] : 0.f;
            float rgt = (d + 4 < 64) ? row[d + 4] : 0.f;
            float4 o;
            o.x = ud0 * lft + ud1 * a0 + ud2 * a1;
            o.y = ud0 * a0  + ud1 * a1 + ud2 * a2;
            o.z = ud0 * a1  + ud1 * a2 + ud2 * a3;
            o.w = ud0 * a2  + ud1 * a3 + ud2 * rgt;
            Bo[q] = o;
        }

        // commit staged plane h+2 into raw[(h+2)%3] (== sm_ slot)
        if (hh < 7) {
            #pragma unroll
            for (int i = 0; i < 4; i++) {
                int q = t + i * 256;
                *(float4*)&raw[sm_ * 4096 + q * 4] = stg[i];
            }
        }
        __syncthreads();   // raw ready for next iter; qs reads done
    }
}

// ---------------------------------------------------------------------------
// K4 (tensor, pipelined): out[b,co,p] = sum_r Uout[r,co] * t[b,r,p] + bias
// Same pipelining as k1; K-depth 64. Dynamic smem 53248 B.
// ---------------------------------------------------------------------------
__global__ void __launch_bounds__(256) k4_mma(const float* __restrict__ Uout,
                                              const float* __restrict__ bias,
                                              float* __restrict__ out) {
    extern __shared__ unsigned dsmu[];
    unsigned* sU = dsmu;                 // Uout [r][co], ld=72
    unsigned* sT = dsmu + RANK * 72;     // t tile [r][p], ld=136

    int b      = blockIdx.x >> 9;
    int p_base = (blockIdx.x & 511) << 9;
    int t      = threadIdx.x;

    {
        const float4* U4 = (const float4*)Uout;
        for (int i = t; i < RANK * COUT / 4; i += 256) {
            int r = i >> 4, c4 = i & 15;
            float4 v = U4[i];
            unsigned* dst = &sU[r * 72 + 4 * c4];
            dst[0] = f2tf(v.x); dst[1] = f2tf(v.y);
            dst[2] = f2tf(v.z); dst[3] = f2tf(v.w);
        }
    }

    const float4* T4 = (const float4*)(g_bufB + (size_t)b * RANK * PVOL);
    int j  = t & 31;
    int r0r = t >> 5;     // rank rows r0r + 8s

    float4 stg[8];
    #pragma unroll
    for (int s = 0; s < 8; s++)
        stg[s] = __ldg(&T4[(size_t)(r0r + 8 * s) * (PVOL / 4) + (p_base >> 2) + j]);
    #pragma unroll
    for (int s = 0; s < 8; s++) {
        uint4 u = make_uint4(f2tf(stg[s].x), f2tf(stg[s].y),
                             f2tf(stg[s].z), f2tf(stg[s].w));
        *(uint4*)&sT[(r0r + 8 * s) * 136 + 4 * j] = u;
    }
    __syncthreads();

    int lane = t & 31, wid = t >> 5;
    int g = lane >> 2, tg = lane & 3;
    int c0 = (wid >> 1) * 16;
    int pW = (wid & 1) * 64;

    unsigned A[8][4];
    #pragma unroll
    for (int ks = 0; ks < 8; ks++) {
        A[ks][0] = sU[(ks * 8 + tg) * 72 + c0 + g];
        A[ks][1] = sU[(ks * 8 + tg) * 72 + c0 + g + 8];
        A[ks][2] = sU[(ks * 8 + tg + 4) * 72 + c0 + g];
        A[ks][3] = sU[(ks * 8 + tg + 4) * 72 + c0 + g + 8];
    }

    float bv0 = __ldg(&bias[c0 + g]);
    float bv1 = __ldg(&bias[c0 + g + 8]);

    #pragma unroll
    for (int tt = 0; tt < 4; tt++) {
        int p0 = p_base + tt * 128;

        if (tt < 3) {
            #pragma unroll
            for (int s = 0; s < 8; s++)
                stg[s] = __ldg(&T4[(size_t)(r0r + 8 * s) * (PVOL / 4)
                                   + ((p0 + 128) >> 2) + j]);
        }

        float C[8][4];
        #pragma unroll
        for (int ni = 0; ni < 8; ni++)
            #pragma unroll
            for (int q = 0; q < 4; q++) C[ni][q] = 0.0f;

        #pragma unroll
        for (int ks = 0; ks < 8; ks++) {
            #pragma unroll
            for (int ni = 0; ni < 8; ni++) {
                unsigned b0 = sT[(ks * 8 + tg) * 136 + pW + 8 * ni + g];
                unsigned b1 = sT[(ks * 8 + tg + 4) * 136 + pW + 8 * ni + g];
                mma_tf32(C[ni], A[ks], b0, b1);
            }
        }

        #pragma unroll
        for (int ni = 0; ni < 8; ni++) {
            int p = p0 + pW + 8 * ni + 2 * tg;
            size_t o0 = (size_t)(b * COUT + c0 + g) * PVOL + p;
            size_t o1 = (size_t)(b * COUT + c0 + g + 8) * PVOL + p;
            *(float2*)&out[o0] = make_float2(C[ni][0] + bv0, C[ni][1] + bv0);
            *(float2*)&out[o1] = make_float2(C[ni][2] + bv1, C[ni][3] + bv1);
        }

        if (tt < 3) {
            __syncthreads();
            #pragma unroll
            for (int s = 0; s < 8; s++) {
                uint4 u = make_uint4(f2tf(stg[s].x), f2tf(stg[s].y),
                                     f2tf(stg[s].z), f2tf(stg[s].w));
                *(uint4*)&sT[(r0r + 8 * s) * 136 + 4 * j] = u;
            }
            __syncthreads();
        }
    }
}

// ---------------------------------------------------------------------------
extern "C" void kernel_launch(void* const* d_in, const int* in_sizes, int n_in,
                              void* d_out, int out_size) {
    const float* x    = (const float*)d_in[0];
    const float* Uh   = (const float*)d_in[1];
    const float* Uw   = (const float*)d_in[2];
    const float* Ud   = (const float*)d_in[3];
    const float* Win  = (const float*)d_in[4];
    const float* Uout = (const float*)d_in[5];
    const float* bias = (const float*)d_in[6];
    float* out = (float*)d_out;

    const int k4_smem  = (RANK * 72 + RANK * 136) * 4;           // 53248
    const int k23_smem = (3 * 4096 + 2 * 64 * 68) * 4;           // 83968
    cudaFuncSetAttribute(k4_mma, cudaFuncAttributeMaxDynamicSharedMemorySize,
                         k4_smem);
    cudaFuncSetAttribute(k23_stream, cudaFuncAttributeMaxDynamicSharedMemorySize,
                         k23_smem);

    k1_mma<<<SB * 512, 256>>>(x, Win);
    k23_stream<<<SB * RANK * 8, 256, k23_smem>>>(Uh, Uw, Ud);
    k4_mma<<<SB * 512, 256, k4_smem>>>(Uout, bias, out);
}

// round 5
// speedup vs baseline: 2.7842x; 1.0377x over previous
#include <cuda_runtime.h>

#define SB   2
#define CIN  32
#define COUT 64
#define RANK 64
#define S    64
#define PVOL (S*S*S)   // 262144

// Scratch (alloc-free rule: device globals). 134 MB each.
// g_bufB holds tf32-bit-pattern values (written by k23, consumed by k4).
__device__ float g_bufA[(size_t)SB * RANK * PVOL];
__device__ float g_bufB[(size_t)SB * RANK * PVOL];

// ---------------------------------------------------------------------------
// helpers
// ---------------------------------------------------------------------------
__device__ __forceinline__ unsigned f2tf(float f) {
    unsigned u;
    asm("cvt.rna.tf32.f32 %0, %1;" : "=r"(u) : "f"(f));
    return u;
}

__device__ __forceinline__ void mma_tf32(float c[4], const unsigned a[4],
                                         const unsigned b0, const unsigned b1) {
    asm volatile(
        "mma.sync.aligned.m16n8k8.row.col.f32.tf32.tf32.f32 "
        "{%0,%1,%2,%3}, {%4,%5,%6,%7}, {%8,%9}, {%0,%1,%2,%3};"
        : "+f"(c[0]), "+f"(c[1]), "+f"(c[2]), "+f"(c[3])
        : "r"(a[0]), "r"(a[1]), "r"(a[2]), "r"(a[3]), "r"(b0), "r"(b1));
}

__device__ __forceinline__ void cp_async16(unsigned saddr, const void* gptr) {
    asm volatile("cp.async.cg.shared.global [%0], [%1], 16;\n"
                 :: "r"(saddr), "l"(gptr));
}
__device__ __forceinline__ void cp_commit() {
    asm volatile("cp.async.commit_group;\n");
}
__device__ __forceinline__ void cp_wait0() {
    asm volatile("cp.async.wait_group 0;\n");
}

// ---------------------------------------------------------------------------
// K1 (tensor, pipelined): y[b,r,p] = sum_c Win[c,r] * x[b,c,p]
// (unchanged from R4 — near its traffic floor)
// ---------------------------------------------------------------------------
__global__ void __launch_bounds__(256) k1_mma(const float* __restrict__ x,
                                              const float* __restrict__ Win) {
    __shared__ unsigned sW[CIN * 72];
    __shared__ unsigned sX[CIN * 136];

    int b      = blockIdx.x >> 9;
    int p_base = (blockIdx.x & 511) << 9;
    int t      = threadIdx.x;

    {
        const float4* W4 = (const float4*)Win;
        for (int i = t; i < CIN * RANK / 4; i += 256) {
            int c = i >> 4, r4 = i & 15;
            float4 v = W4[i];
            unsigned* dst = &sW[c * 72 + 4 * r4];
            dst[0] = f2tf(v.x); dst[1] = f2tf(v.y);
            dst[2] = f2tf(v.z); dst[3] = f2tf(v.w);
        }
    }

    const float4* x4 = (const float4*)(x + (size_t)b * CIN * PVOL);
    int j  = t & 31;
    int c0 = t >> 5;

    float4 stg[4];
    #pragma unroll
    for (int s = 0; s < 4; s++)
        stg[s] = __ldg(&x4[(size_t)(c0 + 8 * s) * (PVOL / 4) + (p_base >> 2) + j]);
    #pragma unroll
    for (int s = 0; s < 4; s++) {
        uint4 u = make_uint4(f2tf(stg[s].x), f2tf(stg[s].y),
                             f2tf(stg[s].z), f2tf(stg[s].w));
        *(uint4*)&sX[(c0 + 8 * s) * 136 + 4 * j] = u;
    }
    __syncthreads();

    int lane = t & 31, wid = t >> 5;
    int g = lane >> 2, tg = lane & 3;
    int r0 = (wid >> 1) * 16;
    int pW = (wid & 1) * 64;

    unsigned A[4][4];
    #pragma unroll
    for (int ks = 0; ks < 4; ks++) {
        A[ks][0] = sW[(ks * 8 + tg) * 72 + r0 + g];
        A[ks][1] = sW[(ks * 8 + tg) * 72 + r0 + g + 8];
        A[ks][2] = sW[(ks * 8 + tg + 4) * 72 + r0 + g];
        A[ks][3] = sW[(ks * 8 + tg + 4) * 72 + r0 + g + 8];
    }

    #pragma unroll
    for (int tt = 0; tt < 4; tt++) {
        int p0 = p_base + tt * 128;

        if (tt < 3) {
            #pragma unroll
            for (int s = 0; s < 4; s++)
                stg[s] = __ldg(&x4[(size_t)(c0 + 8 * s) * (PVOL / 4)
                                   + ((p0 + 128) >> 2) + j]);
        }

        float C[8][4];
        #pragma unroll
        for (int ni = 0; ni < 8; ni++)
            #pragma unroll
            for (int q = 0; q < 4; q++) C[ni][q] = 0.0f;

        #pragma unroll
        for (int ks = 0; ks < 4; ks++) {
            #pragma unroll
            for (int ni = 0; ni < 8; ni++) {
                unsigned b0 = sX[(ks * 8 + tg) * 136 + pW + 8 * ni + g];
                unsigned b1 = sX[(ks * 8 + tg + 4) * 136 + pW + 8 * ni + g];
                mma_tf32(C[ni], A[ks], b0, b1);
            }
        }

        #pragma unroll
        for (int ni = 0; ni < 8; ni++) {
            int p = p0 + pW + 8 * ni + 2 * tg;
            size_t o0 = (size_t)(b * RANK + r0 + g) * PVOL + p;
            size_t o1 = (size_t)(b * RANK + r0 + g + 8) * PVOL + p;
            *(float2*)&g_bufA[o0] = make_float2(C[ni][0], C[ni][1]);
            *(float2*)&g_bufA[o1] = make_float2(C[ni][2], C[ni][3]);
        }

        if (tt < 3) {
            __syncthreads();
            #pragma unroll
            for (int s = 0; s < 4; s++) {
                uint4 u = make_uint4(f2tf(stg[s].x), f2tf(stg[s].y),
                                     f2tf(stg[s].z), f2tf(stg[s].w));
                *(uint4*)&sX[(c0 + 8 * s) * 136 + 4 * j] = u;
            }
            __syncthreads();
        }
    }
}

// ---------------------------------------------------------------------------
// K23 (streaming): fused h/w/d taps; output stored as tf32 bits for k4.
// ---------------------------------------------------------------------------
__global__ void __launch_bounds__(256) k23_stream(const float* __restrict__ Uh,
                                                  const float* __restrict__ Uw,
                                                  const float* __restrict__ Ud) {
    extern __shared__ float dsm[];
    float* raw = dsm;                  // 3 * 4096
    float* hq  = dsm + 3 * 4096;       // 64*68
    float* qs  = hq + 64 * 68;

    int blk = blockIdx.x;
    int hc = blk & 7;
    int r  = (blk >> 3) & 63;
    int b  = blk >> 9;
    int h0 = hc * 8;
    size_t rbase = (size_t)(b * RANK + r) * PVOL;
    int t = threadIdx.x;

    float uh0 = __ldg(&Uh[r]), uh1 = __ldg(&Uh[64 + r]), uh2 = __ldg(&Uh[128 + r]);
    float uw0 = __ldg(&Uw[r]), uw1 = __ldg(&Uw[64 + r]), uw2 = __ldg(&Uw[128 + r]);
    float ud0 = __ldg(&Ud[r]), ud1 = __ldg(&Ud[64 + r]), ud2 = __ldg(&Ud[128 + r]);

    const float4 z4 = make_float4(0.f, 0.f, 0.f, 0.f);

    #pragma unroll
    for (int k = -1; k <= 1; k++) {
        int hp = h0 + k;
        int slot = (hp + 3) % 3;
        const float4* src = (const float4*)(g_bufA + rbase + (size_t)hp * 4096);
        #pragma unroll
        for (int i = 0; i < 4; i++) {
            int q = t + i * 256;
            float4 v = (hp >= 0 && hp < 64) ? __ldg(&src[q]) : z4;
            *(float4*)&raw[slot * 4096 + q * 4] = v;
        }
    }
    __syncthreads();

    for (int hh = 0; hh < 8; hh++) {
        int h = h0 + hh;
        int sm_ = (h + 2) % 3;
        int s0  = h % 3;
        int sp  = (h + 1) % 3;

        #pragma unroll
        for (int i = 0; i < 4; i++) {
            int q = t + i * 256;
            int w = q >> 4, d4 = q & 15;
            float4 vm = *(const float4*)&raw[sm_ * 4096 + q * 4];
            float4 v0 = *(const float4*)&raw[s0 * 4096 + q * 4];
            float4 vp = *(const float4*)&raw[sp * 4096 + q * 4];
            float4 o;
            o.x = uh0 * vm.x + uh1 * v0.x + uh2 * vp.x;
            o.y = uh0 * vm.y + uh1 * v0.y + uh2 * vp.y;
            o.z = uh0 * vm.z + uh1 * v0.z + uh2 * vp.z;
            o.w = uh0 * vm.w + uh1 * v0.w + uh2 * vp.w;
            *(float4*)&hq[w * 68 + d4 * 4] = o;
        }
        __syncthreads();

        float4 stg[4];
        int hn = h + 2;
        if (hh < 7) {
            const float4* src = (const float4*)(g_bufA + rbase + (size_t)hn * 4096);
            #pragma unroll
            for (int i = 0; i < 4; i++) {
                int q = t + i * 256;
                stg[i] = (hn < 64) ? __ldg(&src[q]) : z4;
            }
        }

        #pragma unroll
        for (int i = 0; i < 4; i++) {
            int q = t + i * 256;
            int w = q >> 4, d4 = q & 15;
            float4 c0 = *(const float4*)&hq[w * 68 + d4 * 4];
            float4 m = z4, p = z4;
            if (w > 0)  m = *(const float4*)&hq[(w - 1) * 68 + d4 * 4];
            if (w < 63) p = *(const float4*)&hq[(w + 1) * 68 + d4 * 4];
            float4 o;
            o.x = uw0 * m.x + uw1 * c0.x + uw2 * p.x;
            o.y = uw0 * m.y + uw1 * c0.y + uw2 * p.y;
            o.z = uw0 * m.z + uw1 * c0.z + uw2 * p.z;
            o.w = uw0 * m.w + uw1 * c0.w + uw2 * p.w;
            *(float4*)&qs[w * 68 + d4 * 4] = o;
        }
        __syncthreads();

        // d-tap -> tf32 bits -> gmem (k4 consumes without conversion)
        uint4* Bo = (uint4*)(g_bufB + rbase + (size_t)h * 4096);
        #pragma unroll
        for (int i = 0; i < 4; i++) {
            int q = t + i * 256;
            int w = q >> 4, d4 = q & 15;
            int d = d4 * 4;
            const float* row = &qs[w * 68];
            float a0 = row[d], a1 = row[d + 1], a2 = row[d + 2], a3 = row[d + 3];
            float lft = (d > 0)      ? row[d - 1] : 0.f;
            float rgt = (d + 4 < 64) ? row[d + 4] : 0.f;
            uint4 o;
            o.x = f2tf(ud0 * lft + ud1 * a0 + ud2 * a1);
            o.y = f2tf(ud0 * a0  + ud1 * a1 + ud2 * a2);
            o.z = f2tf(ud0 * a1  + ud1 * a2 + ud2 * a3);
            o.w = f2tf(ud0 * a2  + ud1 * a3 + ud2 * rgt);
            Bo[q] = o;
        }

        if (hh < 7) {
            #pragma unroll
            for (int i = 0; i < 4; i++) {
                int q = t + i * 256;
                *(float4*)&raw[sm_ * 4096 + q * 4] = stg[i];
            }
        }
        __syncthreads();
    }
}

// ---------------------------------------------------------------------------
// K4 (tensor, cp.async double-buffered): out = Uout^T * t + bias
// B tiles arrive as tf32 bits via cp.async; no conversion, no reg staging.
// Dynamic smem: sU 64*72 + 2 * (64*136) u32 = 88064 B.
// ---------------------------------------------------------------------------
__global__ void __launch_bounds__(256) k4_mma(const float* __restrict__ Uout,
                                              const float* __restrict__ bias,
                                              float* __restrict__ out) {
    extern __shared__ unsigned dsmu[];
    unsigned* sU  = dsmu;                    // Uout [r][co], ld=72
    unsigned* sT0 = dsmu + RANK * 72;        // tile buffers, ld=136
    unsigned* sT1 = sT0 + RANK * 136;

    int b      = blockIdx.x >> 9;
    int p_base = (blockIdx.x & 511) << 9;
    int t      = threadIdx.x;

    const float* Tbase = g_bufB + (size_t)b * RANK * PVOL;   // tf32 bits

    // issue tile0 async
    {
        unsigned sa = (unsigned)__cvta_generic_to_shared(sT0);
        #pragma unroll
        for (int i = 0; i < 8; i++) {
            int idx = t + 256 * i;
            int r = idx >> 5, j = idx & 31;
            cp_async16(sa + (r * 136 + 4 * j) * 4,
                       Tbase + (size_t)r * PVOL + p_base + 4 * j);
        }
        cp_commit();
    }

    // fill sU (convert weights to tf32)
    {
        const float4* U4 = (const float4*)Uout;
        for (int i = t; i < RANK * COUT / 4; i += 256) {
            int r = i >> 4, c4 = i & 15;
            float4 v = U4[i];
            unsigned* dst = &sU[r * 72 + 4 * c4];
            dst[0] = f2tf(v.x); dst[1] = f2tf(v.y);
            dst[2] = f2tf(v.z); dst[3] = f2tf(v.w);
        }
    }
    cp_wait0();
    __syncthreads();

    int lane = t & 31, wid = t >> 5;
    int g = lane >> 2, tg = lane & 3;
    int c0 = (wid >> 1) * 16;
    int pW = (wid & 1) * 64;

    unsigned A[8][4];
    #pragma unroll
    for (int ks = 0; ks < 8; ks++) {
        A[ks][0] = sU[(ks * 8 + tg) * 72 + c0 + g];
        A[ks][1] = sU[(ks * 8 + tg) * 72 + c0 + g + 8];
        A[ks][2] = sU[(ks * 8 + tg + 4) * 72 + c0 + g];
        A[ks][3] = sU[(ks * 8 + tg + 4) * 72 + c0 + g + 8];
    }

    float bv0 = __ldg(&bias[c0 + g]);
    float bv1 = __ldg(&bias[c0 + g + 8]);

    #pragma unroll
    for (int tt = 0; tt < 4; tt++) {
        int p0 = p_base + tt * 128;
        unsigned* cur = (tt & 1) ? sT1 : sT0;
        unsigned* nxt = (tt & 1) ? sT0 : sT1;

        if (tt < 3) {
            unsigned sa = (unsigned)__cvta_generic_to_shared(nxt);
            #pragma unroll
            for (int i = 0; i < 8; i++) {
                int idx = t + 256 * i;
                int r = idx >> 5, j = idx & 31;
                cp_async16(sa + (r * 136 + 4 * j) * 4,
                           Tbase + (size_t)r * PVOL + p0 + 128 + 4 * j);
            }
            cp_commit();
        }

        float C[8][4];
        #pragma unroll
        for (int ni = 0; ni < 8; ni++)
            #pragma unroll
            for (int q = 0; q < 4; q++) C[ni][q] = 0.0f;

        #pragma unroll
        for (int ks = 0; ks < 8; ks++) {
            #pragma unroll
            for (int ni = 0; ni < 8; ni++) {
                unsigned b0 = cur[(ks * 8 + tg) * 136 + pW + 8 * ni + g];
                unsigned b1 = cur[(ks * 8 + tg + 4) * 136 + pW + 8 * ni + g];
                mma_tf32(C[ni], A[ks], b0, b1);
            }
        }

        #pragma unroll
        for (int ni = 0; ni < 8; ni++) {
            int p = p0 + pW + 8 * ni + 2 * tg;
            size_t o0 = (size_t)(b * COUT + c0 + g) * PVOL + p;
            size_t o1 = (size_t)(b * COUT + c0 + g + 8) * PVOL + p;
            *(float2*)&out[o0] = make_float2(C[ni][0] + bv0, C[ni][1] + bv0);
            *(float2*)&out[o1] = make_float2(C[ni][2] + bv1, C[ni][3] + bv1);
        }

        if (tt < 3) {
            cp_wait0();
            __syncthreads();
        }
    }
}

// ---------------------------------------------------------------------------
extern "C" void kernel_launch(void* const* d_in, const int* in_sizes, int n_in,
                              void* d_out, int out_size) {
    const float* x    = (const float*)d_in[0];
    const float* Uh   = (const float*)d_in[1];
    const float* Uw   = (const float*)d_in[2];
    const float* Ud   = (const float*)d_in[3];
    const float* Win  = (const float*)d_in[4];
    const float* Uout = (const float*)d_in[5];
    const float* bias = (const float*)d_in[6];
    float* out = (float*)d_out;

    const int k4_smem  = (RANK * 72 + 2 * RANK * 136) * 4;      // 88064
    const int k23_smem = (3 * 4096 + 2 * 64 * 68) * 4;          // 83968
    cudaFuncSetAttribute(k4_mma, cudaFuncAttributeMaxDynamicSharedMemorySize,
                         k4_smem);
    cudaFuncSetAttribute(k23_stream, cudaFuncAttributeMaxDynamicSharedMemorySize,
                         k23_smem);

    k1_mma<<<SB * 512, 256>>>(x, Win);
    k23_stream<<<SB * RANK * 8, 256, k23_smem>>>(Uh, Uw, Ud);
    k4_mma<<<SB * 512, 256, k4_smem>>>(Uout, bias, out);
}

// round 6
// speedup vs baseline: 2.9585x; 1.0626x over previous
#include <cuda_runtime.h>

#define SB   2
#define CIN  32
#define COUT 64
#define RANK 64
#define S    64
#define PVOL (S*S*S)   // 262144

// Scratch (alloc-free rule: device globals). 134 MB each.
// g_bufB holds tf32-bit-pattern values (written by k23, consumed by k4).
__device__ float g_bufA[(size_t)SB * RANK * PVOL];
__device__ float g_bufB[(size_t)SB * RANK * PVOL];

// ---------------------------------------------------------------------------
// helpers
// ---------------------------------------------------------------------------
__device__ __forceinline__ unsigned f2tf(float f) {
    unsigned u;
    asm("cvt.rna.tf32.f32 %0, %1;" : "=r"(u) : "f"(f));
    return u;
}

__device__ __forceinline__ void mma_tf32(float c[4], const unsigned a[4],
                                         const unsigned b0, const unsigned b1) {
    asm volatile(
        "mma.sync.aligned.m16n8k8.row.col.f32.tf32.tf32.f32 "
        "{%0,%1,%2,%3}, {%4,%5,%6,%7}, {%8,%9}, {%0,%1,%2,%3};"
        : "+f"(c[0]), "+f"(c[1]), "+f"(c[2]), "+f"(c[3])
        : "r"(a[0]), "r"(a[1]), "r"(a[2]), "r"(a[3]), "r"(b0), "r"(b1));
}

__device__ __forceinline__ void cp_async16(unsigned saddr, const void* gptr) {
    asm volatile("cp.async.cg.shared.global [%0], [%1], 16;\n"
                 :: "r"(saddr), "l"(gptr));
}
// predicated: src-size 0 -> zero fill (for out-of-range halo planes)
__device__ __forceinline__ void cp_async16p(unsigned saddr, const void* gptr,
                                            bool pred) {
    int sz = pred ? 16 : 0;
    asm volatile("cp.async.cg.shared.global [%0], [%1], 16, %2;\n"
                 :: "r"(saddr), "l"(gptr), "r"(sz));
}
__device__ __forceinline__ void cp_commit() {
    asm volatile("cp.async.commit_group;\n");
}
__device__ __forceinline__ void cp_wait0() {
    asm volatile("cp.async.wait_group 0;\n");
}

// ---------------------------------------------------------------------------
// K1 (tensor, cp.async double-buffered): y[b,r,p] = sum_c Win[c,r] * x[b,c,p]
// Raw fp32 x tiles stream via cp.async; cvt.rna.tf32 applied post-LDS in the
// mma loop (numerically identical to converting before store).
// ---------------------------------------------------------------------------
__global__ void __launch_bounds__(256) k1_mma(const float* __restrict__ x,
                                              const float* __restrict__ Win) {
    __shared__ unsigned sW[CIN * 72];      // tf32 weights [c][r], ld=72
    __shared__ float    sX[2][CIN * 136];  // raw fp32 x tiles [c][p], ld=136

    int b      = blockIdx.x >> 9;
    int p_base = (blockIdx.x & 511) << 9;   // 4 tiles x 128
    int t      = threadIdx.x;

    const float* xb = x + (size_t)b * CIN * PVOL;

    // issue tile 0
    {
        unsigned sa = (unsigned)__cvta_generic_to_shared(&sX[0][0]);
        #pragma unroll
        for (int i = 0; i < 4; i++) {
            int idx = t + 256 * i;
            int c = idx >> 5, j = idx & 31;
            cp_async16(sa + (c * 136 + 4 * j) * 4,
                       xb + (size_t)c * PVOL + p_base + 4 * j);
        }
        cp_commit();
    }

    // fill sW (tf32)
    {
        const float4* W4 = (const float4*)Win;
        for (int i = t; i < CIN * RANK / 4; i += 256) {
            int c = i >> 4, r4 = i & 15;
            float4 v = W4[i];
            unsigned* dst = &sW[c * 72 + 4 * r4];
            dst[0] = f2tf(v.x); dst[1] = f2tf(v.y);
            dst[2] = f2tf(v.z); dst[3] = f2tf(v.w);
        }
    }
    cp_wait0();
    __syncthreads();

    int lane = t & 31, wid = t >> 5;
    int g = lane >> 2, tg = lane & 3;
    int r0 = (wid >> 1) * 16;
    int pW = (wid & 1) * 64;

    unsigned A[4][4];
    #pragma unroll
    for (int ks = 0; ks < 4; ks++) {
        A[ks][0] = sW[(ks * 8 + tg) * 72 + r0 + g];
        A[ks][1] = sW[(ks * 8 + tg) * 72 + r0 + g + 8];
        A[ks][2] = sW[(ks * 8 + tg + 4) * 72 + r0 + g];
        A[ks][3] = sW[(ks * 8 + tg + 4) * 72 + r0 + g + 8];
    }

    #pragma unroll
    for (int tt = 0; tt < 4; tt++) {
        int p0 = p_base + tt * 128;
        const float* cur = sX[tt & 1];

        if (tt < 3) {
            unsigned sa = (unsigned)__cvta_generic_to_shared(&sX[(tt + 1) & 1][0]);
            #pragma unroll
            for (int i = 0; i < 4; i++) {
                int idx = t + 256 * i;
                int c = idx >> 5, j = idx & 31;
                cp_async16(sa + (c * 136 + 4 * j) * 4,
                           xb + (size_t)c * PVOL + p0 + 128 + 4 * j);
            }
            cp_commit();
        }

        float C[8][4];
        #pragma unroll
        for (int ni = 0; ni < 8; ni++)
            #pragma unroll
            for (int q = 0; q < 4; q++) C[ni][q] = 0.0f;

        #pragma unroll
        for (int ks = 0; ks < 4; ks++) {
            #pragma unroll
            for (int ni = 0; ni < 8; ni++) {
                unsigned b0 = f2tf(cur[(ks * 8 + tg) * 136 + pW + 8 * ni + g]);
                unsigned b1 = f2tf(cur[(ks * 8 + tg + 4) * 136 + pW + 8 * ni + g]);
                mma_tf32(C[ni], A[ks], b0, b1);
            }
        }

        #pragma unroll
        for (int ni = 0; ni < 8; ni++) {
            int p = p0 + pW + 8 * ni + 2 * tg;
            size_t o0 = (size_t)(b * RANK + r0 + g) * PVOL + p;
            size_t o1 = (size_t)(b * RANK + r0 + g + 8) * PVOL + p;
            *(float2*)&g_bufA[o0] = make_float2(C[ni][0], C[ni][1]);
            *(float2*)&g_bufA[o1] = make_float2(C[ni][2], C[ni][3]);
        }

        if (tt < 3) {
            cp_wait0();
            __syncthreads();
        }
    }
}

// ---------------------------------------------------------------------------
// K23 (streaming, cp.async ring): fused h/w/d taps; tf32-bit output for k4.
// Block owns (b, r, h-octet); raw planes stream through a 3-slot smem ring.
// ---------------------------------------------------------------------------
__global__ void __launch_bounds__(256) k23_stream(const float* __restrict__ Uh,
                                                  const float* __restrict__ Uw,
                                                  const float* __restrict__ Ud) {
    extern __shared__ float dsm[];
    float* raw = dsm;                  // 3 * 4096
    float* hq  = dsm + 3 * 4096;       // 64*68
    float* qs  = hq + 64 * 68;

    int blk = blockIdx.x;
    int hc = blk & 7;
    int r  = (blk >> 3) & 63;
    int b  = blk >> 9;
    int h0 = hc * 8;
    size_t rbase = (size_t)(b * RANK + r) * PVOL;
    int t = threadIdx.x;

    float uh0 = __ldg(&Uh[r]), uh1 = __ldg(&Uh[64 + r]), uh2 = __ldg(&Uh[128 + r]);
    float uw0 = __ldg(&Uw[r]), uw1 = __ldg(&Uw[64 + r]), uw2 = __ldg(&Uw[128 + r]);
    float ud0 = __ldg(&Ud[r]), ud1 = __ldg(&Ud[64 + r]), ud2 = __ldg(&Ud[128 + r]);

    const float4 z4 = make_float4(0.f, 0.f, 0.f, 0.f);
    unsigned raw_sa = (unsigned)__cvta_generic_to_shared(raw);

    // prologue: planes h0-1, h0, h0+1 into slots (h%3)
    #pragma unroll
    for (int k = -1; k <= 1; k++) {
        int hp = h0 + k;
        int slot = (hp + 3) % 3;
        bool ok = (hp >= 0 && hp < 64);
        const float* src = g_bufA + rbase + (size_t)hp * 4096;
        #pragma unroll
        for (int i = 0; i < 4; i++) {
            int q = t + i * 256;
            cp_async16p(raw_sa + (slot * 4096 + q * 4) * 4, src + q * 4, ok);
        }
    }
    cp_commit();
    cp_wait0();
    __syncthreads();

    for (int hh = 0; hh < 8; hh++) {
        int h = h0 + hh;
        int sm_ = (h + 2) % 3;     // h-1 slot (becomes h+2 slot after reuse)
        int s0  = h % 3;
        int sp  = (h + 1) % 3;

        // h-tap: raw -> hq
        #pragma unroll
        for (int i = 0; i < 4; i++) {
            int q = t + i * 256;
            int w = q >> 4, d4 = q & 15;
            float4 vm = *(const float4*)&raw[sm_ * 4096 + q * 4];
            float4 v0 = *(const float4*)&raw[s0 * 4096 + q * 4];
            float4 vp = *(const float4*)&raw[sp * 4096 + q * 4];
            float4 o;
            o.x = uh0 * vm.x + uh1 * v0.x + uh2 * vp.x;
            o.y = uh0 * vm.y + uh1 * v0.y + uh2 * vp.y;
            o.z = uh0 * vm.z + uh1 * v0.z + uh2 * vp.z;
            o.w = uh0 * vm.w + uh1 * v0.w + uh2 * vp.w;
            *(float4*)&hq[w * 68 + d4 * 4] = o;
        }
        __syncthreads();   // hq ready; raw[sm_] now free

        // async prefetch plane h+2 into freed slot (overlaps w/d taps)
        if (hh < 7) {
            int hn = h + 2;
            bool ok = (hn < 64);
            const float* src = g_bufA + rbase + (size_t)hn * 4096;
            #pragma unroll
            for (int i = 0; i < 4; i++) {
                int q = t + i * 256;
                cp_async16p(raw_sa + (sm_ * 4096 + q * 4) * 4, src + q * 4, ok);
            }
            cp_commit();
        }

        // w-tap: hq -> qs
        #pragma unroll
        for (int i = 0; i < 4; i++) {
            int q = t + i * 256;
            int w = q >> 4, d4 = q & 15;
            float4 c0 = *(const float4*)&hq[w * 68 + d4 * 4];
            float4 m = z4, p = z4;
            if (w > 0)  m = *(const float4*)&hq[(w - 1) * 68 + d4 * 4];
            if (w < 63) p = *(const float4*)&hq[(w + 1) * 68 + d4 * 4];
            float4 o;
            o.x = uw0 * m.x + uw1 * c0.x + uw2 * p.x;
            o.y = uw0 * m.y + uw1 * c0.y + uw2 * p.y;
            o.z = uw0 * m.z + uw1 * c0.z + uw2 * p.z;
            o.w = uw0 * m.w + uw1 * c0.w + uw2 * p.w;
            *(float4*)&qs[w * 68 + d4 * 4] = o;
        }
        __syncthreads();   // qs ready

        // d-tap -> tf32 bits -> gmem (k4 consumes without conversion)
        uint4* Bo = (uint4*)(g_bufB + rbase + (size_t)h * 4096);
        #pragma unroll
        for (int i = 0; i < 4; i++) {
            int q = t + i * 256;
            int w = q >> 4, d4 = q & 15;
            int d = d4 * 4;
            const float* row = &qs[w * 68];
            float a0 = row[d], a1 = row[d + 1], a2 = row[d + 2], a3 = row[d + 3];
            float lft = (d > 0)      ? row[d - 1] : 0.f;
            float rgt = (d + 4 < 64) ? row[d + 4] : 0.f;
            uint4 o;
            o.x = f2tf(ud0 * lft + ud1 * a0 + ud2 * a1);
            o.y = f2tf(ud0 * a0  + ud1 * a1 + ud2 * a2);
            o.z = f2tf(ud0 * a1  + ud1 * a2 + ud2 * a3);
            o.w = f2tf(ud0 * a2  + ud1 * a3 + ud2 * rgt);
            Bo[q] = o;
        }

        if (hh < 7) cp_wait0();
        __syncthreads();   // raw slot refilled & visible; qs reads done
    }
}

// ---------------------------------------------------------------------------
// K4 (tensor, cp.async double-buffered): out = Uout^T * t + bias
// B tiles arrive as tf32 bits via cp.async; no conversion, no reg staging.
// ---------------------------------------------------------------------------
__global__ void __launch_bounds__(256) k4_mma(const float* __restrict__ Uout,
                                              const float* __restrict__ bias,
                                              float* __restrict__ out) {
    extern __shared__ unsigned dsmu[];
    unsigned* sU  = dsmu;                    // Uout [r][co], ld=72
    unsigned* sT0 = dsmu + RANK * 72;        // tile buffers, ld=136
    unsigned* sT1 = sT0 + RANK * 136;

    int b      = blockIdx.x >> 9;
    int p_base = (blockIdx.x & 511) << 9;
    int t      = threadIdx.x;

    const float* Tbase = g_bufB + (size_t)b * RANK * PVOL;   // tf32 bits

    {
        unsigned sa = (unsigned)__cvta_generic_to_shared(sT0);
        #pragma unroll
        for (int i = 0; i < 8; i++) {
            int idx = t + 256 * i;
            int r = idx >> 5, j = idx & 31;
            cp_async16(sa + (r * 136 + 4 * j) * 4,
                       Tbase + (size_t)r * PVOL + p_base + 4 * j);
        }
        cp_commit();
    }

    {
        const float4* U4 = (const float4*)Uout;
        for (int i = t; i < RANK * COUT / 4; i += 256) {
            int r = i >> 4, c4 = i & 15;
            float4 v = U4[i];
            unsigned* dst = &sU[r * 72 + 4 * c4];
            dst[0] = f2tf(v.x); dst[1] = f2tf(v.y);
            dst[2] = f2tf(v.z); dst[3] = f2tf(v.w);
        }
    }
    cp_wait0();
    __syncthreads();

    int lane = t & 31, wid = t >> 5;
    int g = lane >> 2, tg = lane & 3;
    int c0 = (wid >> 1) * 16;
    int pW = (wid & 1) * 64;

    unsigned A[8][4];
    #pragma unroll
    for (int ks = 0; ks < 8; ks++) {
        A[ks][0] = sU[(ks * 8 + tg) * 72 + c0 + g];
        A[ks][1] = sU[(ks * 8 + tg) * 72 + c0 + g + 8];
        A[ks][2] = sU[(ks * 8 + tg + 4) * 72 + c0 + g];
        A[ks][3] = sU[(ks * 8 + tg + 4) * 72 + c0 + g + 8];
    }

    float bv0 = __ldg(&bias[c0 + g]);
    float bv1 = __ldg(&bias[c0 + g + 8]);

    #pragma unroll
    for (int tt = 0; tt < 4; tt++) {
        int p0 = p_base + tt * 128;
        unsigned* cur = (tt & 1) ? sT1 : sT0;
        unsigned* nxt = (tt & 1) ? sT0 : sT1;

        if (tt < 3) {
            unsigned sa = (unsigned)__cvta_generic_to_shared(nxt);
            #pragma unroll
            for (int i = 0; i < 8; i++) {
                int idx = t + 256 * i;
                int r = idx >> 5, j = idx & 31;
                cp_async16(sa + (r * 136 + 4 * j) * 4,
                           Tbase + (size_t)r * PVOL + p0 + 128 + 4 * j);
            }
            cp_commit();
        }

        float C[8][4];
        #pragma unroll
        for (int ni = 0; ni < 8; ni++)
            #pragma unroll
            for (int q = 0; q < 4; q++) C[ni][q] = 0.0f;

        #pragma unroll
        for (int ks = 0; ks < 8; ks++) {
            #pragma unroll
            for (int ni = 0; ni < 8; ni++) {
                unsigned b0 = cur[(ks * 8 + tg) * 136 + pW + 8 * ni + g];
                unsigned b1 = cur[(ks * 8 + tg + 4) * 136 + pW + 8 * ni + g];
                mma_tf32(C[ni], A[ks], b0, b1);
            }
        }

        #pragma unroll
        for (int ni = 0; ni < 8; ni++) {
            int p = p0 + pW + 8 * ni + 2 * tg;
            size_t o0 = (size_t)(b * COUT + c0 + g) * PVOL + p;
            size_t o1 = (size_t)(b * COUT + c0 + g + 8) * PVOL + p;
            *(float2*)&out[o0] = make_float2(C[ni][0] + bv0, C[ni][1] + bv0);
            *(float2*)&out[o1] = make_float2(C[ni][2] + bv1, C[ni][3] + bv1);
        }

        if (tt < 3) {
            cp_wait0();
            __syncthreads();
        }
    }
}

// ---------------------------------------------------------------------------
extern "C" void kernel_launch(void* const* d_in, const int* in_sizes, int n_in,
                              void* d_out, int out_size) {
    const float* x    = (const float*)d_in[0];
    const float* Uh   = (const float*)d_in[1];
    const float* Uw   = (const float*)d_in[2];
    const float* Ud   = (const float*)d_in[3];
    const float* Win  = (const float*)d_in[4];
    const float* Uout = (const float*)d_in[5];
    const float* bias = (const float*)d_in[6];
    float* out = (float*)d_out;

    const int k4_smem  = (RANK * 72 + 2 * RANK * 136) * 4;      // 88064
    const int k23_smem = (3 * 4096 + 2 * 64 * 68) * 4;          // 83968
    cudaFuncSetAttribute(k4_mma, cudaFuncAttributeMaxDynamicSharedMemorySize,
                         k4_smem);
    cudaFuncSetAttribute(k23_stream, cudaFuncAttributeMaxDynamicSharedMemorySize,
                         k23_smem);

    k1_mma<<<SB * 512, 256>>>(x, Win);
    k23_stream<<<SB * RANK * 8, 256, k23_smem>>>(Uh, Uw, Ud);
    k4_mma<<<SB * 512, 256, k4_smem>>>(Uout, bias, out);
}

// round 7
// speedup vs baseline: 3.4708x; 1.1732x over previous
#include <cuda_runtime.h>
#include <cuda_fp16.h>

#define SB   2
#define CIN  32
#define COUT 64
#define RANK 64
#define S    64
#define PVOL (S*S*S)   // 262144

// Scratch (alloc-free rule: device globals). fp16: 67 MB each.
__device__ __half g_bufA[(size_t)SB * RANK * PVOL];
__device__ __half g_bufB[(size_t)SB * RANK * PVOL];

// ---------------------------------------------------------------------------
// helpers
// ---------------------------------------------------------------------------
__device__ __forceinline__ unsigned f2tf(float f) {
    unsigned u;
    asm("cvt.rna.tf32.f32 %0, %1;" : "=r"(u) : "f"(f));
    return u;
}

// fp16 -> fp32 bits (exact; low 13 mantissa bits zero => already valid tf32)
__device__ __forceinline__ unsigned h2tf(__half h) {
    return __float_as_uint(__half2float(h));
}

__device__ __forceinline__ void mma_tf32(float c[4], const unsigned a[4],
                                         const unsigned b0, const unsigned b1) {
    asm volatile(
        "mma.sync.aligned.m16n8k8.row.col.f32.tf32.tf32.f32 "
        "{%0,%1,%2,%3}, {%4,%5,%6,%7}, {%8,%9}, {%0,%1,%2,%3};"
        : "+f"(c[0]), "+f"(c[1]), "+f"(c[2]), "+f"(c[3])
        : "r"(a[0]), "r"(a[1]), "r"(a[2]), "r"(a[3]), "r"(b0), "r"(b1));
}

__device__ __forceinline__ void cp_async16(unsigned saddr, const void* gptr) {
    asm volatile("cp.async.cg.shared.global [%0], [%1], 16;\n"
                 :: "r"(saddr), "l"(gptr));
}
__device__ __forceinline__ void cp_async16p(unsigned saddr, const void* gptr,
                                            bool pred) {
    int sz = pred ? 16 : 0;
    asm volatile("cp.async.cg.shared.global [%0], [%1], 16, %2;\n"
                 :: "r"(saddr), "l"(gptr), "r"(sz));
}
__device__ __forceinline__ void cp_commit() {
    asm volatile("cp.async.commit_group;\n");
}
__device__ __forceinline__ void cp_wait0() {
    asm volatile("cp.async.wait_group 0;\n");
}

// ---------------------------------------------------------------------------
// K1 (tensor, cp.async double-buffered): y[b,r,p] = sum_c Win[c,r] * x[b,c,p]
// x tiles stream fp32 via cp.async; f2tf post-LDS; epilogue stores fp16.
// ---------------------------------------------------------------------------
__global__ void __launch_bounds__(256) k1_mma(const float* __restrict__ x,
                                              const float* __restrict__ Win) {
    __shared__ unsigned sW[CIN * 72];      // tf32 weights [c][r], ld=72
    __shared__ float    sX[2][CIN * 136];  // raw fp32 x tiles [c][p], ld=136

    int b      = blockIdx.x >> 9;
    int p_base = (blockIdx.x & 511) << 9;   // 4 tiles x 128
    int t      = threadIdx.x;

    const float* xb = x + (size_t)b * CIN * PVOL;

    {
        unsigned sa = (unsigned)__cvta_generic_to_shared(&sX[0][0]);
        #pragma unroll
        for (int i = 0; i < 4; i++) {
            int idx = t + 256 * i;
            int c = idx >> 5, j = idx & 31;
            cp_async16(sa + (c * 136 + 4 * j) * 4,
                       xb + (size_t)c * PVOL + p_base + 4 * j);
        }
        cp_commit();
    }

    {
        const float4* W4 = (const float4*)Win;
        for (int i = t; i < CIN * RANK / 4; i += 256) {
            int c = i >> 4, r4 = i & 15;
            float4 v = W4[i];
            unsigned* dst = &sW[c * 72 + 4 * r4];
            dst[0] = f2tf(v.x); dst[1] = f2tf(v.y);
            dst[2] = f2tf(v.z); dst[3] = f2tf(v.w);
        }
    }
    cp_wait0();
    __syncthreads();

    int lane = t & 31, wid = t >> 5;
    int g = lane >> 2, tg = lane & 3;
    int r0 = (wid >> 1) * 16;
    int pW = (wid & 1) * 64;

    unsigned A[4][4];
    #pragma unroll
    for (int ks = 0; ks < 4; ks++) {
        A[ks][0] = sW[(ks * 8 + tg) * 72 + r0 + g];
        A[ks][1] = sW[(ks * 8 + tg) * 72 + r0 + g + 8];
        A[ks][2] = sW[(ks * 8 + tg + 4) * 72 + r0 + g];
        A[ks][3] = sW[(ks * 8 + tg + 4) * 72 + r0 + g + 8];
    }

    #pragma unroll
    for (int tt = 0; tt < 4; tt++) {
        int p0 = p_base + tt * 128;
        const float* cur = sX[tt & 1];

        if (tt < 3) {
            unsigned sa = (unsigned)__cvta_generic_to_shared(&sX[(tt + 1) & 1][0]);
            #pragma unroll
            for (int i = 0; i < 4; i++) {
                int idx = t + 256 * i;
                int c = idx >> 5, j = idx & 31;
                cp_async16(sa + (c * 136 + 4 * j) * 4,
                           xb + (size_t)c * PVOL + p0 + 128 + 4 * j);
            }
            cp_commit();
        }

        float C[8][4];
        #pragma unroll
        for (int ni = 0; ni < 8; ni++)
            #pragma unroll
            for (int q = 0; q < 4; q++) C[ni][q] = 0.0f;

        #pragma unroll
        for (int ks = 0; ks < 4; ks++) {
            #pragma unroll
            for (int ni = 0; ni < 8; ni++) {
                unsigned b0 = f2tf(cur[(ks * 8 + tg) * 136 + pW + 8 * ni + g]);
                unsigned b1 = f2tf(cur[(ks * 8 + tg + 4) * 136 + pW + 8 * ni + g]);
                mma_tf32(C[ni], A[ks], b0, b1);
            }
        }

        #pragma unroll
        for (int ni = 0; ni < 8; ni++) {
            int p = p0 + pW + 8 * ni + 2 * tg;
            size_t o0 = (size_t)(b * RANK + r0 + g) * PVOL + p;
            size_t o1 = (size_t)(b * RANK + r0 + g + 8) * PVOL + p;
            *(__half2*)&g_bufA[o0] = __floats2half2_rn(C[ni][0], C[ni][1]);
            *(__half2*)&g_bufA[o1] = __floats2half2_rn(C[ni][2], C[ni][3]);
        }

        if (tt < 3) {
            cp_wait0();
            __syncthreads();
        }
    }
}

// ---------------------------------------------------------------------------
// K23 (streaming, cp.async ring): fused h/w/d taps on fp16 planes.
// Taps computed in fp32 (hq/qs smem fp32); output stored fp16.
// ---------------------------------------------------------------------------
__global__ void __launch_bounds__(256) k23_stream(const float* __restrict__ Uh,
                                                  const float* __restrict__ Uw,
                                                  const float* __restrict__ Ud) {
    extern __shared__ float dsm[];
    __half* raw = (__half*)dsm;            // 3 planes x 4096 halves (24576 B)
    float* hq  = dsm + 3 * 4096 / 2;       // 64*68 fp32
    float* qs  = hq + 64 * 68;

    int blk = blockIdx.x;
    int hc = blk & 7;
    int r  = (blk >> 3) & 63;
    int b  = blk >> 9;
    int h0 = hc * 8;
    size_t rbase = (size_t)(b * RANK + r) * PVOL;
    int t = threadIdx.x;

    float uh0 = __ldg(&Uh[r]), uh1 = __ldg(&Uh[64 + r]), uh2 = __ldg(&Uh[128 + r]);
    float uw0 = __ldg(&Uw[r]), uw1 = __ldg(&Uw[64 + r]), uw2 = __ldg(&Uw[128 + r]);
    float ud0 = __ldg(&Ud[r]), ud1 = __ldg(&Ud[64 + r]), ud2 = __ldg(&Ud[128 + r]);

    const float4 z4 = make_float4(0.f, 0.f, 0.f, 0.f);
    unsigned raw_sa = (unsigned)__cvta_generic_to_shared(raw);

    // prologue: planes h0-1, h0, h0+1 into slots (h%3). 8 halves per cp (16B).
    #pragma unroll
    for (int k = -1; k <= 1; k++) {
        int hp = h0 + k;
        int slot = (hp + 3) % 3;
        bool ok = (hp >= 0 && hp < 64);
        const __half* src = g_bufA + rbase + (size_t)hp * 4096;
        #pragma unroll
        for (int i = 0; i < 2; i++) {
            int q = t + i * 256;   // chunk of 8 halves, 512 chunks per plane
            cp_async16p(raw_sa + (slot * 4096 + q * 8) * 2, src + q * 8, ok);
        }
    }
    cp_commit();
    cp_wait0();
    __syncthreads();

    for (int hh = 0; hh < 8; hh++) {
        int h = h0 + hh;
        int sm_ = (h + 2) % 3;
        int s0  = h % 3;
        int sp  = (h + 1) % 3;

        // h-tap: raw(fp16) -> hq(fp32). Each thread: 4 chunks of 4 halves.
        #pragma unroll
        for (int i = 0; i < 4; i++) {
            int q = t + i * 256;            // 0..1023, 4 halves each
            int w = q >> 4, d4 = q & 15;
            __half2 m01 = *(__half2*)&raw[sm_ * 4096 + q * 4];
            __half2 m23 = *(__half2*)&raw[sm_ * 4096 + q * 4 + 2];
            __half2 c01 = *(__half2*)&raw[s0  * 4096 + q * 4];
            __half2 c23 = *(__half2*)&raw[s0  * 4096 + q * 4 + 2];
            __half2 p01 = *(__half2*)&raw[sp  * 4096 + q * 4];
            __half2 p23 = *(__half2*)&raw[sp  * 4096 + q * 4 + 2];
            float2 mA = __half22float2(m01), mB = __half22float2(m23);
            float2 cA = __half22float2(c01), cB = __half22float2(c23);
            float2 pA = __half22float2(p01), pB = __half22float2(p23);
            float4 o;
            o.x = uh0 * mA.x + uh1 * cA.x + uh2 * pA.x;
            o.y = uh0 * mA.y + uh1 * cA.y + uh2 * pA.y;
            o.z = uh0 * mB.x + uh1 * cB.x + uh2 * pB.x;
            o.w = uh0 * mB.y + uh1 * cB.y + uh2 * pB.y;
            *(float4*)&hq[w * 68 + d4 * 4] = o;
        }
        __syncthreads();   // hq ready; raw[sm_] now free

        // async prefetch plane h+2 into freed slot (overlaps w/d taps)
        if (hh < 7) {
            int hn = h + 2;
            bool ok = (hn < 64);
            const __half* src = g_bufA + rbase + (size_t)hn * 4096;
            #pragma unroll
            for (int i = 0; i < 2; i++) {
                int q = t + i * 256;
                cp_async16p(raw_sa + (sm_ * 4096 + q * 8) * 2, src + q * 8, ok);
            }
            cp_commit();
        }

        // w-tap: hq -> qs
        #pragma unroll
        for (int i = 0; i < 4; i++) {
            int q = t + i * 256;
            int w = q >> 4, d4 = q & 15;
            float4 c0 = *(const float4*)&hq[w * 68 + d4 * 4];
            float4 m = z4, p = z4;
            if (w > 0)  m = *(const float4*)&hq[(w - 1) * 68 + d4 * 4];
            if (w < 63) p = *(const float4*)&hq[(w + 1) * 68 + d4 * 4];
            float4 o;
            o.x = uw0 * m.x + uw1 * c0.x + uw2 * p.x;
            o.y = uw0 * m.y + uw1 * c0.y + uw2 * p.y;
            o.z = uw0 * m.z + uw1 * c0.z + uw2 * p.z;
            o.w = uw0 * m.w + uw1 * c0.w + uw2 * p.w;
            *(float4*)&qs[w * 68 + d4 * 4] = o;
        }
        __syncthreads();   // qs ready

        // d-tap -> fp16 -> gmem
        __half* Bo = g_bufB + rbase + (size_t)h * 4096;
        #pragma unroll
        for (int i = 0; i < 4; i++) {
            int q = t + i * 256;
            int w = q >> 4, d4 = q & 15;
            int d = d4 * 4;
            const float* row = &qs[w * 68];
            float a0 = row[d], a1 = row[d + 1], a2 = row[d + 2], a3 = row[d + 3];
            float lft = (d > 0)      ? row[d - 1] : 0.f;
            float rgt = (d + 4 < 64) ? row[d + 4] : 0.f;
            __half2 lo = __floats2half2_rn(ud0 * lft + ud1 * a0 + ud2 * a1,
                                           ud0 * a0  + ud1 * a1 + ud2 * a2);
            __half2 hi = __floats2half2_rn(ud0 * a1  + ud1 * a2 + ud2 * a3,
                                           ud0 * a2  + ud1 * a3 + ud2 * rgt);
            *(__half2*)&Bo[q * 4]     = lo;
            *(__half2*)&Bo[q * 4 + 2] = hi;
        }

        if (hh < 7) cp_wait0();
        __syncthreads();
    }
}

// ---------------------------------------------------------------------------
// K4 (tensor, cp.async double-buffered, fp16 B): out = Uout^T * t + bias
// B tiles arrive fp16 via cp.async; h2f post-LDS is exact (valid tf32).
// ---------------------------------------------------------------------------
__global__ void __launch_bounds__(256) k4_mma(const float* __restrict__ Uout,
                                              const float* __restrict__ bias,
                                              float* __restrict__ out) {
    extern __shared__ unsigned dsmu[];
    unsigned* sU  = dsmu;                       // Uout [r][co] tf32, ld=72
    __half*   sT0 = (__half*)(dsmu + RANK * 72);  // fp16 tiles [r][p], ld=136
    __half*   sT1 = sT0 + RANK * 136;

    int b      = blockIdx.x >> 9;
    int p_base = (blockIdx.x & 511) << 9;
    int t      = threadIdx.x;

    const __half* Tbase = g_bufB + (size_t)b * RANK * PVOL;

    // issue tile0 async: 64 rows x 128 halves = 1024 chunks of 8 halves
    {
        unsigned sa = (unsigned)__cvta_generic_to_shared(sT0);
        #pragma unroll
        for (int i = 0; i < 4; i++) {
            int idx = t + 256 * i;
            int r = idx >> 4, j = idx & 15;
            cp_async16(sa + (r * 136 + 8 * j) * 2,
                       Tbase + (size_t)r * PVOL + p_base + 8 * j);
        }
        cp_commit();
    }

    {
        const float4* U4 = (const float4*)Uout;
        for (int i = t; i < RANK * COUT / 4; i += 256) {
            int r = i >> 4, c4 = i & 15;
            float4 v = U4[i];
            unsigned* dst = &sU[r * 72 + 4 * c4];
            dst[0] = f2tf(v.x); dst[1] = f2tf(v.y);
            dst[2] = f2tf(v.z); dst[3] = f2tf(v.w);
        }
    }
    cp_wait0();
    __syncthreads();

    int lane = t & 31, wid = t >> 5;
    int g = lane >> 2, tg = lane & 3;
    int c0 = (wid >> 1) * 16;
    int pW = (wid & 1) * 64;

    unsigned A[8][4];
    #pragma unroll
    for (int ks = 0; ks < 8; ks++) {
        A[ks][0] = sU[(ks * 8 + tg) * 72 + c0 + g];
        A[ks][1] = sU[(ks * 8 + tg) * 72 + c0 + g + 8];
        A[ks][2] = sU[(ks * 8 + tg + 4) * 72 + c0 + g];
        A[ks][3] = sU[(ks * 8 + tg + 4) * 72 + c0 + g + 8];
    }

    float bv0 = __ldg(&bias[c0 + g]);
    float bv1 = __ldg(&bias[c0 + g + 8]);

    #pragma unroll
    for (int tt = 0; tt < 4; tt++) {
        int p0 = p_base + tt * 128;
        const __half* cur = (tt & 1) ? sT1 : sT0;
        __half*       nxt = (tt & 1) ? sT0 : sT1;

        if (tt < 3) {
            unsigned sa = (unsigned)__cvta_generic_to_shared(nxt);
            #pragma unroll
            for (int i = 0; i < 4; i++) {
                int idx = t + 256 * i;
                int r = idx >> 4, j = idx & 15;
                cp_async16(sa + (r * 136 + 8 * j) * 2,
                           Tbase + (size_t)r * PVOL + p0 + 128 + 8 * j);
            }
            cp_commit();
        }

        float C[8][4];
        #pragma unroll
        for (int ni = 0; ni < 8; ni++)
            #pragma unroll
            for (int q = 0; q < 4; q++) C[ni][q] = 0.0f;

        #pragma unroll
        for (int ks = 0; ks < 8; ks++) {
            #pragma unroll
            for (int ni = 0; ni < 8; ni++) {
                unsigned b0 = h2tf(cur[(ks * 8 + tg) * 136 + pW + 8 * ni + g]);
                unsigned b1 = h2tf(cur[(ks * 8 + tg + 4) * 136 + pW + 8 * ni + g]);
                mma_tf32(C[ni], A[ks], b0, b1);
            }
        }

        #pragma unroll
        for (int ni = 0; ni < 8; ni++) {
            int p = p0 + pW + 8 * ni + 2 * tg;
            size_t o0 = (size_t)(b * COUT + c0 + g) * PVOL + p;
            size_t o1 = (size_t)(b * COUT + c0 + g + 8) * PVOL + p;
            *(float2*)&out[o0] = make_float2(C[ni][0] + bv0, C[ni][1] + bv0);
            *(float2*)&out[o1] = make_float2(C[ni][2] + bv1, C[ni][3] + bv1);
        }

        if (tt < 3) {
            cp_wait0();
            __syncthreads();
        }
    }
}

// ---------------------------------------------------------------------------
extern "C" void kernel_launch(void* const* d_in, const int* in_sizes, int n_in,
                              void* d_out, int out_size) {
    const float* x    = (const float*)d_in[0];
    const float* Uh   = (const float*)d_in[1];
    const float* Uw   = (const float*)d_in[2];
    const float* Ud   = (const float*)d_in[3];
    const float* Win  = (const float*)d_in[4];
    const float* Uout = (const float*)d_in[5];
    const float* bias = (const float*)d_in[6];
    float* out = (float*)d_out;

    const int k4_smem  = RANK * 72 * 4 + 2 * RANK * 136 * 2;    // 53248 B
    const int k23_smem = 3 * 4096 * 2 + 2 * 64 * 68 * 4;        // 59392 B
    cudaFuncSetAttribute(k4_mma, cudaFuncAttributeMaxDynamicSharedMemorySize,
                         k4_smem);
    cudaFuncSetAttribute(k23_stream, cudaFuncAttributeMaxDynamicSharedMemorySize,
                         k23_smem);

    k1_mma<<<SB * 512, 256>>>(x, Win);
    k23_stream<<<SB * RANK * 8, 256, k23_smem>>>(Uh, Uw, Ud);
    k4_mma<<<SB * 512, 256, k4_smem>>>(Uout, bias, out);
}

// round 8
// speedup vs baseline: 3.8688x; 1.1147x over previous
#include <cuda_runtime.h>
#include <cuda_fp16.h>

#define SB   2
#define CIN  32
#define COUT 64
#define RANK 64
#define S    64
#define PVOL (S*S*S)   // 262144

// Scratch (alloc-free rule: device globals). fp16: 67 MB each.
__device__ __half g_bufA[(size_t)SB * RANK * PVOL];
__device__ __half g_bufB[(size_t)SB * RANK * PVOL];

// ---------------------------------------------------------------------------
// helpers
// ---------------------------------------------------------------------------
__device__ __forceinline__ unsigned f2tf(float f) {
    unsigned u;
    asm("cvt.rna.tf32.f32 %0, %1;" : "=r"(u) : "f"(f));
    return u;
}

__device__ __forceinline__ void mma_tf32(float c[4], const unsigned a[4],
                                         const unsigned b0, const unsigned b1) {
    asm volatile(
        "mma.sync.aligned.m16n8k8.row.col.f32.tf32.tf32.f32 "
        "{%0,%1,%2,%3}, {%4,%5,%6,%7}, {%8,%9}, {%0,%1,%2,%3};"
        : "+f"(c[0]), "+f"(c[1]), "+f"(c[2]), "+f"(c[3])
        : "r"(a[0]), "r"(a[1]), "r"(a[2]), "r"(a[3]), "r"(b0), "r"(b1));
}

__device__ __forceinline__ void mma_f16(float c[4], const unsigned a[4],
                                        const unsigned b0, const unsigned b1) {
    asm volatile(
        "mma.sync.aligned.m16n8k16.row.col.f32.f16.f16.f32 "
        "{%0,%1,%2,%3}, {%4,%5,%6,%7}, {%8,%9}, {%0,%1,%2,%3};"
        : "+f"(c[0]), "+f"(c[1]), "+f"(c[2]), "+f"(c[3])
        : "r"(a[0]), "r"(a[1]), "r"(a[2]), "r"(a[3]), "r"(b0), "r"(b1));
}

__device__ __forceinline__ void ldsm_x4_trans(unsigned& r0, unsigned& r1,
                                              unsigned& r2, unsigned& r3,
                                              unsigned saddr) {
    asm volatile(
        "ldmatrix.sync.aligned.m8n8.x4.trans.shared.b16 {%0,%1,%2,%3}, [%4];"
        : "=r"(r0), "=r"(r1), "=r"(r2), "=r"(r3) : "r"(saddr));
}

__device__ __forceinline__ void cp_async16(unsigned saddr, const void* gptr) {
    asm volatile("cp.async.cg.shared.global [%0], [%1], 16;\n"
                 :: "r"(saddr), "l"(gptr));
}
__device__ __forceinline__ void cp_async16p(unsigned saddr, const void* gptr,
                                            bool pred) {
    int sz = pred ? 16 : 0;
    asm volatile("cp.async.cg.shared.global [%0], [%1], 16, %2;\n"
                 :: "r"(saddr), "l"(gptr), "r"(sz));
}
__device__ __forceinline__ void cp_commit() {
    asm volatile("cp.async.commit_group;\n");
}
__device__ __forceinline__ void cp_wait0() {
    asm volatile("cp.async.wait_group 0;\n");
}

// ---------------------------------------------------------------------------
// K1 (tf32, cp.async double-buffered, 2Mx4N warps): y = Win^T * x -> fp16
// Warp tile: 32 r x 32 p — B fragments reused by both m-frags.
// ---------------------------------------------------------------------------
__global__ void __launch_bounds__(256) k1_mma(const float* __restrict__ x,
                                              const float* __restrict__ Win) {
    __shared__ unsigned sW[CIN * 72];      // tf32 weights [c][r], ld=72
    __shared__ float    sX[2][CIN * 136];  // raw fp32 x tiles [c][p], ld=136

    int b      = blockIdx.x >> 9;
    int p_base = (blockIdx.x & 511) << 9;   // 4 tiles x 128
    int t      = threadIdx.x;

    const float* xb = x + (size_t)b * CIN * PVOL;

    {
        unsigned sa = (unsigned)__cvta_generic_to_shared(&sX[0][0]);
        #pragma unroll
        for (int i = 0; i < 4; i++) {
            int idx = t + 256 * i;
            int c = idx >> 5, j = idx & 31;
            cp_async16(sa + (c * 136 + 4 * j) * 4,
                       xb + (size_t)c * PVOL + p_base + 4 * j);
        }
        cp_commit();
    }

    {
        const float4* W4 = (const float4*)Win;
        for (int i = t; i < CIN * RANK / 4; i += 256) {
            int c = i >> 4, r4 = i & 15;
            float4 v = W4[i];
            unsigned* dst = &sW[c * 72 + 4 * r4];
            dst[0] = f2tf(v.x); dst[1] = f2tf(v.y);
            dst[2] = f2tf(v.z); dst[3] = f2tf(v.w);
        }
    }
    cp_wait0();
    __syncthreads();

    int lane = t & 31, wid = t >> 5;
    int g = lane >> 2, tg = lane & 3;
    int r0 = (wid & 1) * 32;       // M offset: 2 groups of 32 ranks
    int pW = (wid >> 1) * 32;      // N offset: 4 groups of 32 positions

    unsigned A[4][2][4];
    #pragma unroll
    for (int ks = 0; ks < 4; ks++)
        #pragma unroll
        for (int mm = 0; mm < 2; mm++) {
            int rm = r0 + 16 * mm;
            A[ks][mm][0] = sW[(ks * 8 + tg) * 72 + rm + g];
            A[ks][mm][1] = sW[(ks * 8 + tg) * 72 + rm + g + 8];
            A[ks][mm][2] = sW[(ks * 8 + tg + 4) * 72 + rm + g];
            A[ks][mm][3] = sW[(ks * 8 + tg + 4) * 72 + rm + g + 8];
        }

    #pragma unroll
    for (int tt = 0; tt < 4; tt++) {
        int p0 = p_base + tt * 128;
        const float* cur = sX[tt & 1];

        if (tt < 3) {
            unsigned sa = (unsigned)__cvta_generic_to_shared(&sX[(tt + 1) & 1][0]);
            #pragma unroll
            for (int i = 0; i < 4; i++) {
                int idx = t + 256 * i;
                int c = idx >> 5, j = idx & 31;
                cp_async16(sa + (c * 136 + 4 * j) * 4,
                           xb + (size_t)c * PVOL + p0 + 128 + 4 * j);
            }
            cp_commit();
        }

        float C[2][4][4];
        #pragma unroll
        for (int mm = 0; mm < 2; mm++)
            #pragma unroll
            for (int ni = 0; ni < 4; ni++)
                #pragma unroll
                for (int q = 0; q < 4; q++) C[mm][ni][q] = 0.0f;

        #pragma unroll
        for (int ks = 0; ks < 4; ks++) {
            #pragma unroll
            for (int ni = 0; ni < 4; ni++) {
                unsigned b0 = f2tf(cur[(ks * 8 + tg) * 136 + pW + 8 * ni + g]);
                unsigned b1 = f2tf(cur[(ks * 8 + tg + 4) * 136 + pW + 8 * ni + g]);
                mma_tf32(C[0][ni], A[ks][0], b0, b1);
                mma_tf32(C[1][ni], A[ks][1], b0, b1);
            }
        }

        #pragma unroll
        for (int mm = 0; mm < 2; mm++)
            #pragma unroll
            for (int ni = 0; ni < 4; ni++) {
                int p = p0 + pW + 8 * ni + 2 * tg;
                int rm = r0 + 16 * mm;
                size_t o0 = (size_t)(b * RANK + rm + g) * PVOL + p;
                size_t o1 = (size_t)(b * RANK + rm + g + 8) * PVOL + p;
                *(__half2*)&g_bufA[o0] = __floats2half2_rn(C[mm][ni][0], C[mm][ni][1]);
                *(__half2*)&g_bufA[o1] = __floats2half2_rn(C[mm][ni][2], C[mm][ni][3]);
            }

        if (tt < 3) {
            cp_wait0();
            __syncthreads();
        }
    }
}

// ---------------------------------------------------------------------------
// K23 (streaming, cp.async ring): fused h/w/d taps on fp16 planes (unchanged).
// ---------------------------------------------------------------------------
__global__ void __launch_bounds__(256) k23_stream(const float* __restrict__ Uh,
                                                  const float* __restrict__ Uw,
                                                  const float* __restrict__ Ud) {
    extern __shared__ float dsm[];
    __half* raw = (__half*)dsm;            // 3 planes x 4096 halves
    float* hq  = dsm + 3 * 4096 / 2;       // 64*68 fp32
    float* qs  = hq + 64 * 68;

    int blk = blockIdx.x;
    int hc = blk & 7;
    int r  = (blk >> 3) & 63;
    int b  = blk >> 9;
    int h0 = hc * 8;
    size_t rbase = (size_t)(b * RANK + r) * PVOL;
    int t = threadIdx.x;

    float uh0 = __ldg(&Uh[r]), uh1 = __ldg(&Uh[64 + r]), uh2 = __ldg(&Uh[128 + r]);
    float uw0 = __ldg(&Uw[r]), uw1 = __ldg(&Uw[64 + r]), uw2 = __ldg(&Uw[128 + r]);
    float ud0 = __ldg(&Ud[r]), ud1 = __ldg(&Ud[64 + r]), ud2 = __ldg(&Ud[128 + r]);

    const float4 z4 = make_float4(0.f, 0.f, 0.f, 0.f);
    unsigned raw_sa = (unsigned)__cvta_generic_to_shared(raw);

    #pragma unroll
    for (int k = -1; k <= 1; k++) {
        int hp = h0 + k;
        int slot = (hp + 3) % 3;
        bool ok = (hp >= 0 && hp < 64);
        const __half* src = g_bufA + rbase + (size_t)hp * 4096;
        #pragma unroll
        for (int i = 0; i < 2; i++) {
            int q = t + i * 256;
            cp_async16p(raw_sa + (slot * 4096 + q * 8) * 2, src + q * 8, ok);
        }
    }
    cp_commit();
    cp_wait0();
    __syncthreads();

    for (int hh = 0; hh < 8; hh++) {
        int h = h0 + hh;
        int sm_ = (h + 2) % 3;
        int s0  = h % 3;
        int sp  = (h + 1) % 3;

        #pragma unroll
        for (int i = 0; i < 4; i++) {
            int q = t + i * 256;
            int w = q >> 4, d4 = q & 15;
            __half2 m01 = *(__half2*)&raw[sm_ * 4096 + q * 4];
            __half2 m23 = *(__half2*)&raw[sm_ * 4096 + q * 4 + 2];
            __half2 c01 = *(__half2*)&raw[s0  * 4096 + q * 4];
            __half2 c23 = *(__half2*)&raw[s0  * 4096 + q * 4 + 2];
            __half2 p01 = *(__half2*)&raw[sp  * 4096 + q * 4];
            __half2 p23 = *(__half2*)&raw[sp  * 4096 + q * 4 + 2];
            float2 mA = __half22float2(m01), mB = __half22float2(m23);
            float2 cA = __half22float2(c01), cB = __half22float2(c23);
            float2 pA = __half22float2(p01), pB = __half22float2(p23);
            float4 o;
            o.x = uh0 * mA.x + uh1 * cA.x + uh2 * pA.x;
            o.y = uh0 * mA.y + uh1 * cA.y + uh2 * pA.y;
            o.z = uh0 * mB.x + uh1 * cB.x + uh2 * pB.x;
            o.w = uh0 * mB.y + uh1 * cB.y + uh2 * pB.y;
            *(float4*)&hq[w * 68 + d4 * 4] = o;
        }
        __syncthreads();

        if (hh < 7) {
            int hn = h + 2;
            bool ok = (hn < 64);
            const __half* src = g_bufA + rbase + (size_t)hn * 4096;
            #pragma unroll
            for (int i = 0; i < 2; i++) {
                int q = t + i * 256;
                cp_async16p(raw_sa + (sm_ * 4096 + q * 8) * 2, src + q * 8, ok);
            }
            cp_commit();
        }

        #pragma unroll
        for (int i = 0; i < 4; i++) {
            int q = t + i * 256;
            int w = q >> 4, d4 = q & 15;
            float4 c0 = *(const float4*)&hq[w * 68 + d4 * 4];
            float4 m = z4, p = z4;
            if (w > 0)  m = *(const float4*)&hq[(w - 1) * 68 + d4 * 4];
            if (w < 63) p = *(const float4*)&hq[(w + 1) * 68 + d4 * 4];
            float4 o;
            o.x = uw0 * m.x + uw1 * c0.x + uw2 * p.x;
            o.y = uw0 * m.y + uw1 * c0.y + uw2 * p.y;
            o.z = uw0 * m.z + uw1 * c0.z + uw2 * p.z;
            o.w = uw0 * m.w + uw1 * c0.w + uw2 * p.w;
            *(float4*)&qs[w * 68 + d4 * 4] = o;
        }
        __syncthreads();

        __half* Bo = g_bufB + rbase + (size_t)h * 4096;
        #pragma unroll
        for (int i = 0; i < 4; i++) {
            int q = t + i * 256;
            int w = q >> 4, d4 = q & 15;
            int d = d4 * 4;
            const float* row = &qs[w * 68];
            float a0 = row[d], a1 = row[d + 1], a2 = row[d + 2], a3 = row[d + 3];
            float lft = (d > 0)      ? row[d - 1] : 0.f;
            float rgt = (d + 4 < 64) ? row[d + 4] : 0.f;
            __half2 lo = __floats2half2_rn(ud0 * lft + ud1 * a0 + ud2 * a1,
                                           ud0 * a0  + ud1 * a1 + ud2 * a2);
            __half2 hi = __floats2half2_rn(ud0 * a1  + ud1 * a2 + ud2 * a3,
                                           ud0 * a2  + ud1 * a3 + ud2 * rgt);
            *(__half2*)&Bo[q * 4]     = lo;
            *(__half2*)&Bo[q * 4 + 2] = hi;
        }

        if (hh < 7) cp_wait0();
        __syncthreads();
    }
}

// ---------------------------------------------------------------------------
// K4 (fp16 HMMA + ldmatrix, cp.async double-buffered): out = Uout^T*t + bias
// A = Uout transposed to fp16 smem [co][r]; B = fp16 tiles via ldmatrix.trans.
// ---------------------------------------------------------------------------
__global__ void __launch_bounds__(256) k4_mma(const float* __restrict__ Uout,
                                              const float* __restrict__ bias,
                                              float* __restrict__ out) {
    extern __shared__ __half hsm[];
    __half* sA  = hsm;                 // [co=64][r], ld=72 halves
    __half* sT0 = hsm + 64 * 72;       // fp16 tiles [r][p], ld=136 halves
    __half* sT1 = sT0 + RANK * 136;

    int b      = blockIdx.x >> 9;
    int p_base = (blockIdx.x & 511) << 9;
    int t      = threadIdx.x;

    const __half* Tbase = g_bufB + (size_t)b * RANK * PVOL;

    // issue tile0 async
    {
        unsigned sa = (unsigned)__cvta_generic_to_shared(sT0);
        #pragma unroll
        for (int i = 0; i < 4; i++) {
            int idx = t + 256 * i;
            int r = idx >> 4, j = idx & 15;
            cp_async16(sa + (r * 136 + 8 * j) * 2,
                       Tbase + (size_t)r * PVOL + p_base + 8 * j);
        }
        cp_commit();
    }

    // fill sA: transpose Uout [r][co] -> sA[co][r] as fp16
    #pragma unroll
    for (int i = t; i < RANK * COUT; i += 256) {
        int r = i >> 6, co = i & 63;
        sA[co * 72 + r] = __float2half(Uout[i]);
    }
    cp_wait0();
    __syncthreads();

    int lane = t & 31, wid = t >> 5;
    int g = lane >> 2, tg = lane & 3;
    int c0 = (wid >> 1) * 16;       // M offset (cout)
    int pW = (wid & 1) * 64;        // N offset

    // A fragments (fp16 m16k16): 4 k-groups of 16
    unsigned A[4][4];
    #pragma unroll
    for (int ks = 0; ks < 4; ks++) {
        int kk = ks * 16 + 2 * tg;
        A[ks][0] = *(const unsigned*)&sA[(c0 + g) * 72 + kk];
        A[ks][1] = *(const unsigned*)&sA[(c0 + g + 8) * 72 + kk];
        A[ks][2] = *(const unsigned*)&sA[(c0 + g) * 72 + kk + 8];
        A[ks][3] = *(const unsigned*)&sA[(c0 + g + 8) * 72 + kk + 8];
    }

    float bv0 = __ldg(&bias[c0 + g]);
    float bv1 = __ldg(&bias[c0 + g + 8]);

    // per-lane ldmatrix base offsets
    int lm_row = lane & 15;
    int lm_col = 8 * (lane >> 4);

    #pragma unroll
    for (int tt = 0; tt < 4; tt++) {
        int p0 = p_base + tt * 128;
        __half* cur = (tt & 1) ? sT1 : sT0;
        __half* nxt = (tt & 1) ? sT0 : sT1;

        if (tt < 3) {
            unsigned sa = (unsigned)__cvta_generic_to_shared(nxt);
            #pragma unroll
            for (int i = 0; i < 4; i++) {
                int idx = t + 256 * i;
                int r = idx >> 4, j = idx & 15;
                cp_async16(sa + (r * 136 + 8 * j) * 2,
                           Tbase + (size_t)r * PVOL + p0 + 128 + 8 * j);
            }
            cp_commit();
        }

        float C[8][4];
        #pragma unroll
        for (int ni = 0; ni < 8; ni++)
            #pragma unroll
            for (int q = 0; q < 4; q++) C[ni][q] = 0.0f;

        unsigned cur_sa = (unsigned)__cvta_generic_to_shared(cur);

        #pragma unroll
        for (int ks = 0; ks < 4; ks++) {
            #pragma unroll
            for (int nj = 0; nj < 4; nj++) {
                unsigned b0, b1, b2, b3;
                unsigned addr = cur_sa +
                    ((ks * 16 + lm_row) * 136 + pW + nj * 16 + lm_col) * 2;
                ldsm_x4_trans(b0, b1, b2, b3, addr);
                mma_f16(C[2 * nj],     A[ks], b0, b1);
                mma_f16(C[2 * nj + 1], A[ks], b2, b3);
            }
        }

        #pragma unroll
        for (int ni = 0; ni < 8; ni++) {
            int p = p0 + pW + 8 * ni + 2 * tg;
            size_t o0 = (size_t)(b * COUT + c0 + g) * PVOL + p;
            size_t o1 = (size_t)(b * COUT + c0 + g + 8) * PVOL + p;
            *(float2*)&out[o0] = make_float2(C[ni][0] + bv0, C[ni][1] + bv0);
            *(float2*)&out[o1] = make_float2(C[ni][2] + bv1, C[ni][3] + bv1);
        }

        if (tt < 3) {
            cp_wait0();
            __syncthreads();
        }
    }
}

// ---------------------------------------------------------------------------
extern "C" void kernel_launch(void* const* d_in, const int* in_sizes, int n_in,
                              void* d_out, int out_size) {
    const float* x    = (const float*)d_in[0];
    const float* Uh   = (const float*)d_in[1];
    const float* Uw   = (const float*)d_in[2];
    const float* Ud   = (const float*)d_in[3];
    const float* Win  = (const float*)d_in[4];
    const float* Uout = (const float*)d_in[5];
    const float* bias = (const float*)d_in[6];
    float* out = (float*)d_out;

    const int k4_smem  = (64 * 72 + 2 * RANK * 136) * 2;        // 44032 B
    const int k23_smem = 3 * 4096 * 2 + 2 * 64 * 68 * 4;        // 59392 B
    cudaFuncSetAttribute(k4_mma, cudaFuncAttributeMaxDynamicSharedMemorySize,
                         k4_smem);
    cudaFuncSetAttribute(k23_stream, cudaFuncAttributeMaxDynamicSharedMemorySize,
                         k23_smem);

    k1_mma<<<SB * 512, 256>>>(x, Win);
    k23_stream<<<SB * RANK * 8, 256, k23_smem>>>(Uh, Uw, Ud);
    k4_mma<<<SB * 512, 256, k4_smem>>>(Uout, bias, out);
}